// round 9
// baseline (speedup 1.0000x reference)
#include <cuda_runtime.h>
#include <cuda_bf16.h>
#include <math.h>
#include <stdint.h>

#define BB 8
#define NN 4096
#define KK 16
#define CC 64
#define NPTS (BB*NN*KK)
#define EPSF 1e-6f
#define PI_F 3.14159265358979323846f

// ---------------- device globals ----------------
__device__ double g_mom[34];
__device__ double g_zs1[CC];
__device__ double g_zs2[CC];
__device__ float  g_WcfT[4*CC];
__device__ float  g_bcf[CC];
__device__ float  g_WpfT[5*CC];
__device__ float  g_bpf[CC];
__device__ float  g_Wmain[128*CC];   // [k][c]
__device__ float  g_bz[CC];
__device__ float  g_bp[CC];
__device__ float  g_alpha[CC];
__device__ float  g_beta[CC];
__device__ float  g_z1[CC*NPTS];     // [c][p]
// bf16 split weights [c][k] row-major (contiguous k)
__device__ __nv_bfloat16 g_Whi[CC*128];
__device__ __nv_bfloat16 g_Wlo[CC*128];
__device__ __nv_bfloat16 g_W2hi[CC*CC];
__device__ __nv_bfloat16 g_W2lo[CC*CC];

// ---------------- helpers ----------------
#define MMA_BF16(d0,d1,d2,d3,a0,a1,a2,a3,b0,b1) \
    asm volatile("mma.sync.aligned.m16n8k16.row.col.f32.bf16.bf16.f32 " \
        "{%0,%1,%2,%3}, {%4,%5,%6,%7}, {%8,%9}, {%0,%1,%2,%3};" \
        : "+f"(d0),"+f"(d1),"+f"(d2),"+f"(d3) \
        : "r"(a0),"r"(a1),"r"(a2),"r"(a3),"r"(b0),"r"(b1))

#define LDSM_X4(r0,r1,r2,r3, addr) \
    asm volatile("ldmatrix.sync.aligned.m8n8.x4.shared.b16 {%0,%1,%2,%3}, [%4];" \
        : "=r"(r0),"=r"(r1),"=r"(r2),"=r"(r3) : "r"(addr))

__device__ __forceinline__ uint32_t smem_u32(const void* p){
    uint32_t a;
    asm("{ .reg .u64 t; cvta.to.shared.u64 t, %1; cvt.u32.u64 %0, t; }" : "=r"(a) : "l"(p));
    return a;
}

__device__ __forceinline__ void split2(float v0, float v1, uint32_t& hp, uint32_t& lp){
    __nv_bfloat16 h0 = __float2bfloat16_rn(v0);
    __nv_bfloat16 h1 = __float2bfloat16_rn(v1);
    float r0 = v0 - __bfloat162float(h0);
    float r1 = v1 - __bfloat162float(h1);
    __nv_bfloat16 l0 = __float2bfloat16_rn(r0);
    __nv_bfloat16 l1 = __float2bfloat16_rn(r1);
    hp = (uint32_t)(*(uint16_t*)&h0) | ((uint32_t)(*(uint16_t*)&h1) << 16);
    lp = (uint32_t)(*(uint16_t*)&l0) | ((uint32_t)(*(uint16_t*)&l1) << 16);
}

__device__ __forceinline__ float wsum32(float v){
#pragma unroll
    for (int m=1; m<32; m<<=1) v += __shfl_xor_sync(0xffffffffu, v, m);
    return v;
}
__device__ __forceinline__ float gsum16(float v){
#pragma unroll
    for (int m=1; m<16; m<<=1) v += __shfl_xor_sync(0xffffffffu, v, m);
    return v;
}
__device__ __forceinline__ int clampi(int x,int lo,int hi){return x<lo?lo:(x>hi?hi:x);}

struct Geo { float dx,dy,dz,r,rn,sth,cth,sph,cph,theta; };
__device__ __forceinline__ Geo geom(const float* __restrict__ nxyz,
                                    const float* __restrict__ cxyz, int p){
    int b = p>>16, n = (p>>4)&(NN-1), k = p&(KK-1);
    int cb = (b*3)*NN + n;
    float cx=cxyz[cb], cy=cxyz[cb+NN], cz=cxyz[cb+2*NN];
    int nb = ((b*3)*NN + n)*KK + k;
    Geo g;
    g.dx = nxyz[nb]         - cx;
    g.dy = nxyz[nb+NN*KK]   - cy;
    g.dz = nxyz[nb+2*NN*KK] - cz;
    float r = sqrtf(g.dx*g.dx + g.dy*g.dy + g.dz*g.dz); r = fmaxf(r, EPSF);
    float rho = fmaxf(sqrtf(g.dx*g.dx + g.dy*g.dy), EPSF);
    g.r = r;
    g.theta = atan2f(g.dy, g.dx);
    float phi = atan2f(g.dz, rho);
    float rmean = gsum16(r) * (1.0f/16.0f);
    g.rn = fminf(r/(rmean+EPSF), 3.0f) * (1.0f/3.0f);
    sincosf(g.theta, &g.sth, &g.cth);
    sincosf(phi, &g.sph, &g.cph);
    return g;
}
struct Mix { float c0,c1,c2,c3, m0,m1,m2,m3, s_k; };
__device__ __forceinline__ Mix make_mix(const Geo& g){
    float ridx = g.rn*(2.0f - 1e-6f);
    float aidx = ((g.theta + PI_F)*(0.5f/PI_F))*(12.0f - 1e-6f);
    float ri0f = floorf(ridx); float rw1 = ridx-ri0f, rw0 = 1.0f-rw1;
    int ri0 = clampi((int)ri0f,0,1), ri1 = clampi((int)ri0f+1,0,1);
    float ai0f = floorf(aidx); float aw1 = aidx-ai0f, aw0 = 1.0f-aw1;
    int ai0 = clampi((int)ai0f,0,11), ai1 = clampi((int)ai0f+1,0,11);
    float w00=rw0*aw0, w01=rw0*aw1, w10=rw1*aw0, w11=rw1*aw1;
    int c00=ri0*12+ai0, c01=ri0*12+ai1, c10=ri1*12+ai0, c11=ri1*12+ai1;
    int t0 = __shfl_sync(0xffffffffu, c00, 0, 16);
    int t1 = __shfl_sync(0xffffffffu, c01, 0, 16);
    int t2 = __shfl_sync(0xffffffffu, c10, 0, 16);
    int t3 = __shfl_sync(0xffffffffu, c11, 0, 16);
    Mix mx;
    mx.c0 = (c00==t0?w00:0.f)+(c01==t0?w01:0.f)+(c10==t0?w10:0.f)+(c11==t0?w11:0.f);
    mx.c1 = (c00==t1?w00:0.f)+(c01==t1?w01:0.f)+(c10==t1?w10:0.f)+(c11==t1?w11:0.f);
    mx.c2 = (c00==t2?w00:0.f)+(c01==t2?w01:0.f)+(c10==t2?w10:0.f)+(c11==t2?w11:0.f);
    mx.c3 = (c00==t3?w00:0.f)+(c01==t3?w01:0.f)+(c10==t3?w10:0.f)+(c11==t3?w11:0.f);
    float den0 = gsum16(mx.c0), den1 = gsum16(mx.c1);
    float den2 = gsum16(mx.c2), den3 = gsum16(mx.c3);
    mx.m0 = w00/fmaxf(den0,EPSF); mx.m1 = w01/fmaxf(den1,EPSF);
    mx.m2 = w10/fmaxf(den2,EPSF); mx.m3 = w11/fmaxf(den3,EPSF);
    mx.s_k = mx.m0*den0 + mx.m1*den1 + mx.m2*den2 + mx.m3*den3;
    return mx;
}

// ---------------- small kernels ----------------
__global__ void zero_kernel(){
    int t = threadIdx.x;
    if (t < 34) g_mom[t] = 0.0;
    if (t < CC) { g_zs1[t]=0.0; g_zs2[t]=0.0; }
}

__global__ __launch_bounds__(256) void moments_kernel(const float* __restrict__ nxyz,
                                                      const float* __restrict__ cxyz){
    __shared__ double smom[34];
    int tid = threadIdx.x;
    if (tid < 34) smom[tid] = 0.0;
    __syncthreads();
    int p = blockIdx.x*256 + tid;
    Geo g = geom(nxyz, cxyz, p);
    float fc[4] = {g.dx, g.dy, g.dz, g.r};
    float fp[5] = {g.rn, g.sth, g.cth, g.sph, g.cph};
    float v[34];
#pragma unroll
    for (int i=0;i<4;i++){
        v[i] = fc[i];
#pragma unroll
        for (int j=i;j<4;j++) v[4 + i*4 - (i*(i-1))/2 + (j-i)] = fc[i]*fc[j];
    }
#pragma unroll
    for (int i=0;i<5;i++){
        v[14+i] = fp[i];
#pragma unroll
        for (int j=i;j<5;j++) v[19 + i*5 - (i*(i-1))/2 + (j-i)] = fp[i]*fp[j];
    }
#pragma unroll
    for (int i=0;i<34;i++){
        float s = wsum32(v[i]);
        if ((tid&31)==0) atomicAdd(&smom[i], (double)s);
    }
    __syncthreads();
    if (tid < 34) atomicAdd(&g_mom[tid], smom[tid]);
}

__global__ void setup_kernel(
    const float* __restrict__ cf_w1, const float* __restrict__ cf_b1,
    const float* __restrict__ cf_g,  const float* __restrict__ cf_be,
    const float* __restrict__ cf_w2, const float* __restrict__ cf_b2,
    const float* __restrict__ pf_w1, const float* __restrict__ pf_b1,
    const float* __restrict__ pf_g,  const float* __restrict__ pf_be,
    const float* __restrict__ pf_w2, const float* __restrict__ pf_b2,
    const float* __restrict__ ac_w,  const float* __restrict__ ac_b,
    const float* __restrict__ ap_w,  const float* __restrict__ ap_b,
    const float* __restrict__ gamma_p,
    const float* __restrict__ ge_w1, const float* __restrict__ ge_b1,
    const float* __restrict__ ge_w2)
{
    __shared__ float sT[CC*CC];
    __shared__ float sv1[CC], sv2[CC];
    int tid = threadIdx.x;
    float gam = gamma_p[0];
    const double inv = 1.0/(double)NPTS;

    if (tid < CC){
        { // cart BN fold
            double mu[4], cov[4][4];
#pragma unroll
            for (int i=0;i<4;i++) mu[i] = g_mom[i]*inv;
#pragma unroll
            for (int i=0;i<4;i++)
#pragma unroll
                for (int j=i;j<4;j++){
                    double c2 = g_mom[4 + i*4 - (i*(i-1))/2 + (j-i)]*inv - mu[i]*mu[j];
                    cov[i][j]=c2; cov[j][i]=c2;
                }
            double w[4], m=(double)cf_b1[tid], vv=0.0;
#pragma unroll
            for (int i=0;i<4;i++){ w[i]=(double)cf_w1[tid*4+i]; m += w[i]*mu[i]; }
#pragma unroll
            for (int i=0;i<4;i++)
#pragma unroll
                for (int j=0;j<4;j++) vv += w[i]*w[j]*cov[i][j];
            double al = (double)cf_g[tid]/sqrt(vv+1e-5);
#pragma unroll
            for (int i=0;i<4;i++) g_WcfT[i*CC+tid] = (float)(w[i]*al);
            g_bcf[tid] = (float)(((double)cf_b1[tid]-m)*al + (double)cf_be[tid]);
        }
        { // polar BN fold
            double mu[5], cov[5][5];
#pragma unroll
            for (int i=0;i<5;i++) mu[i] = g_mom[14+i]*inv;
#pragma unroll
            for (int i=0;i<5;i++)
#pragma unroll
                for (int j=i;j<5;j++){
                    double c2 = g_mom[19 + i*5 - (i*(i-1))/2 + (j-i)]*inv - mu[i]*mu[j];
                    cov[i][j]=c2; cov[j][i]=c2;
                }
            double w[5], m=(double)pf_b1[tid], vv=0.0;
#pragma unroll
            for (int i=0;i<5;i++){ w[i]=(double)pf_w1[tid*5+i]; m += w[i]*mu[i]; }
#pragma unroll
            for (int i=0;i<5;i++)
#pragma unroll
                for (int j=0;j<5;j++) vv += w[i]*w[j]*cov[i][j];
            double al = (double)pf_g[tid]/sqrt(vv+1e-5);
#pragma unroll
            for (int i=0;i<5;i++) g_WpfT[i*CC+tid] = (float)(w[i]*al);
            g_bpf[tid] = (float)(((double)pf_b1[tid]-m)*al + (double)pf_be[tid]);
        }
    }
    for (int e=tid;e<CC*CC;e+=blockDim.x){
        int m=e>>6, j=e&63; float s=0.f;
        for (int l=0;l<CC;l++) s += ac_w[m*CC+l]*cf_w2[l*CC+j];
        sT[e]=s;
    }
    __syncthreads();
    for (int e=tid;e<CC*CC;e+=blockDim.x){
        int c=e>>6, j=e&63; float s=0.f;
        for (int m=0;m<CC;m++) s += ge_w1[c*CC+m]*sT[m*CC+j];
        g_Wmain[j*CC+c]=s;
    }
    __syncthreads();
    for (int e=tid;e<CC*CC;e+=blockDim.x){
        int m=e>>6, j=e&63; float s=0.f;
        for (int l=0;l<CC;l++) s += ap_w[m*CC+l]*pf_w2[l*CC+j];
        sT[e]=s;
    }
    __syncthreads();
    for (int e=tid;e<CC*CC;e+=blockDim.x){
        int c=e>>6, j=e&63; float s=0.f;
        for (int m=0;m<CC;m++) s += ge_w1[c*CC+m]*sT[m*CC+j];
        g_Wmain[(64+j)*CC+c]=gam*s;
    }
    if (tid < CC){
        float s1 = ac_b[tid] + gam*ap_b[tid];
        for (int j=0;j<CC;j++) s1 += ac_w[tid*CC+j]*cf_b2[j];
        sv1[tid]=s1;
        float s2 = 0.f;
        for (int j=0;j<CC;j++) s2 += ap_w[tid*CC+j]*pf_b2[j];
        sv2[tid]=s2;
    }
    __syncthreads();
    if (tid < CC){
        float bz = ge_b1[tid], bp = 0.f;
        for (int m=0;m<CC;m++){ bz += ge_w1[tid*CC+m]*sv1[m]; bp += ge_w1[tid*CC+m]*sv2[m]; }
        g_bz[tid]=bz; g_bp[tid]=gam*bp;
    }
    __syncthreads();
    for (int e=tid; e<CC*128; e+=blockDim.x){
        int k = e & 127, c = e >> 7;
        float v = g_Wmain[k*CC + c];
        __nv_bfloat16 h = __float2bfloat16_rn(v);
        float rem = v - __bfloat162float(h);
        g_Whi[c*128 + k] = h;
        g_Wlo[c*128 + k] = __float2bfloat16_rn(rem);
    }
    for (int e=tid; e<CC*CC; e+=blockDim.x){
        int j = e & 63, c = e >> 6;
        float v = ge_w2[c*CC + j];
        __nv_bfloat16 h = __float2bfloat16_rn(v);
        float rem = v - __bfloat162float(h);
        g_W2hi[c*64 + j] = h;
        g_W2lo[c*64 + j] = __float2bfloat16_rn(rem);
    }
}

// ---------------- main kernel smem layout (bytes) ----------------
#define HSTR 136   // 272B row stride; 68 words == 4 mod 32 -> conflict-free LDSM
#define WSTR 136
#define SH_HHI   0          // 128*272 = 34816
#define SH_HLO   34816      // -> 69632
#define SH_WHI   69632      // 64*272 = 17408 -> 87040
#define SH_WLO   87040      // -> 104448
#define SH_HP    104448     // 32768 -> 137216
#define SH_GEO   137216     // 4608 -> 141824
#define SH_CC    141824     // 2048 (reused as stats S1)
#define SH_MM    143872     // 2048 (reused as stats S2)
#define SH_SK    145920     // 512
#define SH_WCF   146432     // 1024
#define SH_WPF   147456     // 1280
#define SH_BCF   148736     // 256
#define SH_BPF   148992     // 256
#define SH_BZ    149248     // 256
#define SH_BP    149504     // 256
#define MAIN_SMEM 149760

__global__ __launch_bounds__(256,1) void main_kernel(const float* __restrict__ nxyz,
                                                     const float* __restrict__ cxyz){
    extern __shared__ char smc[];
    float* sHPf = (float*)(smc + SH_HP);
    float* sGEO = (float*)(smc + SH_GEO);
    float* sCc  = (float*)(smc + SH_CC);
    float* sMm  = (float*)(smc + SH_MM);
    float* sSK  = (float*)(smc + SH_SK);
    float* sWcf = (float*)(smc + SH_WCF);
    float* sWpf = (float*)(smc + SH_WPF);
    float* sbcf = (float*)(smc + SH_BCF);
    float* sbpf = (float*)(smc + SH_BPF);
    float* sbz  = (float*)(smc + SH_BZ);
    float* sbp  = (float*)(smc + SH_BP);
    int tid = threadIdx.x;
    int wid = tid >> 5;
    int lane = tid & 31;

    // phase 0: weights into smem (padded W tiles for ldmatrix)
    {
        int c = tid >> 2, q = tid & 3;
        const uint4* gh = (const uint4*)(g_Whi + c*128 + q*32);
        const uint4* gl = (const uint4*)(g_Wlo + c*128 + q*32);
        uint4* shh = (uint4*)(smc + SH_WHI + (c*WSTR + q*32)*2);
        uint4* shl = (uint4*)(smc + SH_WLO + (c*WSTR + q*32)*2);
#pragma unroll
        for (int i=0;i<4;i++){ shh[i]=gh[i]; shl[i]=gl[i]; }
    }
    for (int i=tid;i<4*CC;i+=256) sWcf[i]=g_WcfT[i];
    for (int i=tid;i<5*CC;i+=256) sWpf[i]=g_WpfT[i];
    if (tid < CC){
        sbcf[tid]=g_bcf[tid]; sbpf[tid]=g_bpf[tid];
        sbz[tid]=g_bz[tid];   sbp[tid]=g_bp[tid];
    }
    __syncthreads();

    int p0 = blockIdx.x*128;

    // phase A: geometry + mix coeffs (threads 0-127)
    if (tid < 128){
        Geo g = geom(nxyz, cxyz, p0 + tid);
        Mix mx = make_mix(g);
        sGEO[0*128+tid]=g.dx;  sGEO[1*128+tid]=g.dy;  sGEO[2*128+tid]=g.dz;
        sGEO[3*128+tid]=g.r;   sGEO[4*128+tid]=g.rn;  sGEO[5*128+tid]=g.sth;
        sGEO[6*128+tid]=g.cth; sGEO[7*128+tid]=g.sph; sGEO[8*128+tid]=g.cph;
        sCc[0*128+tid]=mx.c0; sCc[1*128+tid]=mx.c1; sCc[2*128+tid]=mx.c2; sCc[3*128+tid]=mx.c3;
        sMm[0*128+tid]=mx.m0; sMm[1*128+tid]=mx.m1; sMm[2*128+tid]=mx.m2; sMm[3*128+tid]=mx.m3;
        sSK[tid]=mx.s_k;
    }
    __syncthreads();

    // phase B: first layers
    {
        int m = tid & 127;
        int jh = (tid >> 7) * 32;
        float dx=sGEO[m],     dy=sGEO[128+m], dz=sGEO[256+m], r =sGEO[384+m];
        float rn=sGEO[512+m], st=sGEO[640+m], ct=sGEO[768+m];
        float sp=sGEO[896+m], cp=sGEO[1024+m];
        char* Hhi = smc + SH_HHI;
        char* Hlo = smc + SH_HLO;
#pragma unroll 4
        for (int j=jh; j<jh+32; j+=2){
            float h0 = sbcf[j];
            h0 = fmaf(dx,sWcf[j],h0); h0 = fmaf(dy,sWcf[64+j],h0);
            h0 = fmaf(dz,sWcf[128+j],h0); h0 = fmaf(r,sWcf[192+j],h0);
            h0 = fmaxf(h0,0.f);
            float h1 = sbcf[j+1];
            h1 = fmaf(dx,sWcf[j+1],h1); h1 = fmaf(dy,sWcf[64+j+1],h1);
            h1 = fmaf(dz,sWcf[128+j+1],h1); h1 = fmaf(r,sWcf[192+j+1],h1);
            h1 = fmaxf(h1,0.f);
            uint32_t hp, lp; split2(h0, h1, hp, lp);
            uint32_t off = (uint32_t)(m*HSTR + j)*2;
            *(uint32_t*)(Hhi + off) = hp;
            *(uint32_t*)(Hlo + off) = lp;
            float q0 = sbpf[j];
            q0 = fmaf(rn,sWpf[j],q0); q0 = fmaf(st,sWpf[64+j],q0);
            q0 = fmaf(ct,sWpf[128+j],q0); q0 = fmaf(sp,sWpf[192+j],q0);
            q0 = fmaf(cp,sWpf[256+j],q0);
            sHPf[j*128+m] = fmaxf(q0,0.f);
            float q1 = sbpf[j+1];
            q1 = fmaf(rn,sWpf[j+1],q1); q1 = fmaf(st,sWpf[64+j+1],q1);
            q1 = fmaf(ct,sWpf[128+j+1],q1); q1 = fmaf(sp,sWpf[192+j+1],q1);
            q1 = fmaf(cp,sWpf[256+j+1],q1);
            sHPf[(j+1)*128+m] = fmaxf(q1,0.f);
        }
    }
    __syncthreads();

    // mix: 512 tasks
#pragma unroll
    for (int t2i=0;t2i<2;t2i++){
        int tk = t2i*256 + tid;
        int j = tk>>3, grp = tk&7;
        float* hrow = sHPf + j*128 + grp*16;
        const float* cb = sCc + grp*16;
        const float* mb = sMm + grp*16;
        float h[16];
#pragma unroll
        for (int k=0;k<16;k++) h[k]=hrow[k];
        float g0=0.f,g1=0.f,g2=0.f,g3=0.f;
#pragma unroll
        for (int k=0;k<16;k++){
            g0 = fmaf(cb[0*128+k], h[k], g0);
            g1 = fmaf(cb[1*128+k], h[k], g1);
            g2 = fmaf(cb[2*128+k], h[k], g2);
            g3 = fmaf(cb[3*128+k], h[k], g3);
        }
#pragma unroll
        for (int k=0;k<16;k++){
            float o = mb[0*128+k]*g0;
            o = fmaf(mb[1*128+k], g1, o);
            o = fmaf(mb[2*128+k], g2, o);
            o = fmaf(mb[3*128+k], g3, o);
            hrow[k] = o;
        }
    }
    __syncthreads();

    // convert polar to bf16 H cols 64..127; zero stats staging
    {
        int m = tid & 127;
        int ch = (tid >> 7) * 32;
        char* Hhi = smc + SH_HHI;
        char* Hlo = smc + SH_HLO;
#pragma unroll 4
        for (int jj=ch; jj<ch+32; jj+=2){
            float v0 = sHPf[jj*128+m];
            float v1 = sHPf[(jj+1)*128+m];
            uint32_t hp, lp; split2(v0, v1, hp, lp);
            uint32_t off = (uint32_t)(m*HSTR + 64 + jj)*2;
            *(uint32_t*)(Hhi + off) = hp;
            *(uint32_t*)(Hlo + off) = lp;
        }
    }
    if (tid < CC){ sCc[tid]=0.f; sMm[tid]=0.f; }
    __syncthreads();

    // GEMM via mma.sync bf16, ldmatrix fragment feeds
    {
        int g = lane >> 2;
        int t2 = (lane & 3) * 2;
        int c0 = (wid & 3) * 16;
        int ph = (wid >> 2) * 64;
        int r0 = c0 + g, r1 = c0 + g + 8;
        int lrow = lane & 7, lgrp = lane >> 3;

        // A fragments from padded W smem
        uint32_t Ah[8][4], Al[8][4];
        {
            uint32_t arow = (uint32_t)(c0 + (lgrp & 1)*8 + lrow);
            uint32_t acol = (uint32_t)((lgrp >> 1) * 8);
            uint32_t bh = smem_u32(smc + SH_WHI) + (arow*WSTR + acol)*2;
            uint32_t bl = smem_u32(smc + SH_WLO) + (arow*WSTR + acol)*2;
#pragma unroll
            for (int ks=0; ks<8; ks++){
                LDSM_X4(Ah[ks][0],Ah[ks][1],Ah[ks][2],Ah[ks][3], bh + ks*32);
                LDSM_X4(Al[ks][0],Al[ks][1],Al[ks][2],Al[ks][3], bl + ks*32);
            }
        }
        uint32_t hbase = smem_u32(smc + SH_HHI);
        uint32_t lbase = smem_u32(smc + SH_HLO);
        float bz0 = sbz[r0], bz1 = sbz[r1], bp0 = sbp[r0], bp1 = sbp[r1];
        float s10=0.f, s20=0.f, s11=0.f, s21=0.f;
#pragma unroll 1
        for (int nt=0; nt<8; nt++){
            int pn = ph + nt*8;
            uint32_t badh = hbase + (uint32_t)((pn + lrow)*HSTR + lgrp*8)*2;
            uint32_t badl = lbase + (uint32_t)((pn + lrow)*HSTR + lgrp*8)*2;
            uint32_t Bh[16], Bl[16];
#pragma unroll
            for (int kq=0; kq<4; kq++){
                LDSM_X4(Bh[kq*4+0],Bh[kq*4+1],Bh[kq*4+2],Bh[kq*4+3], badh + kq*64);
                LDSM_X4(Bl[kq*4+0],Bl[kq*4+1],Bl[kq*4+2],Bl[kq*4+3], badl + kq*64);
            }
            float a0=0.f, a1=0.f, a2=0.f, a3=0.f;
#pragma unroll
            for (int ks=0; ks<8; ks++){
                uint32_t bh0 = Bh[2*ks], bh1 = Bh[2*ks+1];
                uint32_t bl0 = Bl[2*ks], bl1 = Bl[2*ks+1];
                MMA_BF16(a0,a1,a2,a3, Ah[ks][0],Ah[ks][1],Ah[ks][2],Ah[ks][3], bh0,bh1);
                MMA_BF16(a0,a1,a2,a3, Ah[ks][0],Ah[ks][1],Ah[ks][2],Ah[ks][3], bl0,bl1);
                MMA_BF16(a0,a1,a2,a3, Al[ks][0],Al[ks][1],Al[ks][2],Al[ks][3], bh0,bh1);
            }
            int col = pn + t2;
            float sk0 = sSK[col], sk1 = sSK[col+1];
            float z00 = a0 + fmaf(bp0, sk0, bz0);
            float z01 = a1 + fmaf(bp0, sk1, bz0);
            float z10 = a2 + fmaf(bp1, sk0, bz1);
            float z11 = a3 + fmaf(bp1, sk1, bz1);
            *(float2*)(g_z1 + (size_t)r0*NPTS + p0 + col) = make_float2(z00,z01);
            *(float2*)(g_z1 + (size_t)r1*NPTS + p0 + col) = make_float2(z10,z11);
            s10 += z00+z01; s20 += z00*z00+z01*z01;
            s11 += z10+z11; s21 += z10*z10+z11*z11;
        }
        s10 += __shfl_xor_sync(0xffffffffu, s10, 1); s10 += __shfl_xor_sync(0xffffffffu, s10, 2);
        s20 += __shfl_xor_sync(0xffffffffu, s20, 1); s20 += __shfl_xor_sync(0xffffffffu, s20, 2);
        s11 += __shfl_xor_sync(0xffffffffu, s11, 1); s11 += __shfl_xor_sync(0xffffffffu, s11, 2);
        s21 += __shfl_xor_sync(0xffffffffu, s21, 1); s21 += __shfl_xor_sync(0xffffffffu, s21, 2);
        if ((lane & 3) == 0){
            atomicAdd(&sCc[r0], s10); atomicAdd(&sMm[r0], s20);
            atomicAdd(&sCc[r1], s11); atomicAdd(&sMm[r1], s21);
        }
    }
    __syncthreads();
    if (tid < CC){
        atomicAdd(&g_zs1[tid], (double)sCc[tid]);
        atomicAdd(&g_zs2[tid], (double)sMm[tid]);
    }
}

__global__ void bnstats_kernel(const float* __restrict__ ge_g, const float* __restrict__ ge_be){
    int c = threadIdx.x;
    if (c < CC){
        double mean = g_zs1[c]/(double)NPTS;
        double var  = g_zs2[c]/(double)NPTS - mean*mean;
        double a = (double)ge_g[c]/sqrt(var + 1e-5);
        g_alpha[c] = (float)a;
        g_beta[c]  = (float)((double)ge_be[c] - mean*a);
    }
}

// ---------------- final kernel ----------------
#define FSTR 72    // 144B stride; 36 words == 4 mod 32 -> conflict-free LDSM
#define F2STR 72
#define FH_HHI 0        // 128*144 = 18432
#define FH_HLO 18432    // -> 36864
#define FH_WHI 36864    // 64*144 = 9216 -> 46080
#define FH_WLO 46080    // -> 55296
#define FH_A   55296    // 256
#define FH_BV  55552    // 256
#define FH_B2  55808    // 256
#define FINAL_SMEM 56064

__global__ __launch_bounds__(256,2) void final_kernel(const float* __restrict__ ge_b2,
                                                      float* __restrict__ out){
    extern __shared__ char smc[];
    float* sa  = (float*)(smc + FH_A);
    float* sbv = (float*)(smc + FH_BV);
    float* sb2 = (float*)(smc + FH_B2);
    int tid = threadIdx.x;
    int wid = tid >> 5;
    int lane = tid & 31;

    // W2 copy into padded smem
    {
        int c = tid >> 2, q = tid & 3;   // 16 elems per (c,q)
        const uint4* gh = (const uint4*)(g_W2hi + c*64 + q*16);
        const uint4* gl = (const uint4*)(g_W2lo + c*64 + q*16);
        uint4* shh = (uint4*)(smc + FH_WHI + (c*F2STR + q*16)*2);
        uint4* shl = (uint4*)(smc + FH_WLO + (c*F2STR + q*16)*2);
#pragma unroll
        for (int i=0;i<2;i++){ shh[i]=gh[i]; shl[i]=gl[i]; }
    }
    if (tid < CC){ sa[tid]=g_alpha[tid]; sbv[tid]=g_beta[tid]; sb2[tid]=ge_b2[tid]; }
    __syncthreads();

    int p0 = blockIdx.x*128;

    // phase 1: load z, affine+relu, bf16 split -> H2[p][c]
    {
        int m = tid & 127;
        int ch = (tid >> 7) * 32;
        char* Hhi = smc + FH_HHI;
        char* Hlo = smc + FH_HLO;
#pragma unroll 4
        for (int c=ch; c<ch+32; c+=2){
            float z0 = g_z1[(size_t)c*NPTS + p0 + m];
            float z1v = g_z1[(size_t)(c+1)*NPTS + p0 + m];
            float h0 = fmaxf(fmaf(z0, sa[c], sbv[c]), 0.f);
            float h1 = fmaxf(fmaf(z1v, sa[c+1], sbv[c+1]), 0.f);
            uint32_t hp, lp; split2(h0, h1, hp, lp);
            uint32_t off = (uint32_t)(m*FSTR + c)*2;
            *(uint32_t*)(Hhi + off) = hp;
            *(uint32_t*)(Hlo + off) = lp;
        }
    }
    __syncthreads();

    {
        int g = lane >> 2;
        int t2 = (lane & 3) * 2;
        int c0 = (wid & 3) * 16;
        int ph = (wid >> 2) * 64;
        int r0 = c0 + g, r1 = c0 + g + 8;
        int lrow = lane & 7, lgrp = lane >> 3;

        uint32_t Ah[4][4], Al[4][4];
        {
            uint32_t arow = (uint32_t)(c0 + (lgrp & 1)*8 + lrow);
            uint32_t acol = (uint32_t)((lgrp >> 1) * 8);
            uint32_t bh = smem_u32(smc + FH_WHI) + (arow*F2STR + acol)*2;
            uint32_t bl = smem_u32(smc + FH_WLO) + (arow*F2STR + acol)*2;
#pragma unroll
            for (int ks=0; ks<4; ks++){
                LDSM_X4(Ah[ks][0],Ah[ks][1],Ah[ks][2],Ah[ks][3], bh + ks*32);
                LDSM_X4(Al[ks][0],Al[ks][1],Al[ks][2],Al[ks][3], bl + ks*32);
            }
        }
        uint32_t hbase = smem_u32(smc + FH_HHI);
        uint32_t lbase = smem_u32(smc + FH_HLO);
        float b0v = sb2[r0], b1v = sb2[r1];
        int b = p0 >> 16;
        int nk0 = p0 & 65535;
        float* ob = out + (size_t)b*CC*65536;
#pragma unroll 1
        for (int nt=0; nt<8; nt++){
            int pn = ph + nt*8;
            uint32_t badh = hbase + (uint32_t)((pn + lrow)*FSTR + lgrp*8)*2;
            uint32_t badl = lbase + (uint32_t)((pn + lrow)*FSTR + lgrp*8)*2;
            uint32_t Bh[8], Bl[8];
#pragma unroll
            for (int kq=0; kq<2; kq++){
                LDSM_X4(Bh[kq*4+0],Bh[kq*4+1],Bh[kq*4+2],Bh[kq*4+3], badh + kq*64);
                LDSM_X4(Bl[kq*4+0],Bl[kq*4+1],Bl[kq*4+2],Bl[kq*4+3], badl + kq*64);
            }
            float a0=0.f, a1=0.f, a2=0.f, a3=0.f;
#pragma unroll
            for (int ks=0; ks<4; ks++){
                uint32_t bh0 = Bh[2*ks], bh1 = Bh[2*ks+1];
                uint32_t bl0 = Bl[2*ks], bl1 = Bl[2*ks+1];
                MMA_BF16(a0,a1,a2,a3, Ah[ks][0],Ah[ks][1],Ah[ks][2],Ah[ks][3], bh0,bh1);
                MMA_BF16(a0,a1,a2,a3, Ah[ks][0],Ah[ks][1],Ah[ks][2],Ah[ks][3], bl0,bl1);
                MMA_BF16(a0,a1,a2,a3, Al[ks][0],Al[ks][1],Al[ks][2],Al[ks][3], bh0,bh1);
            }
            int col = pn + t2;
            *(float2*)(ob + (size_t)r0*65536 + nk0 + col) = make_float2(a0+b0v, a1+b0v);
            *(float2*)(ob + (size_t)r1*65536 + nk0 + col) = make_float2(a2+b1v, a3+b1v);
        }
    }
}

extern "C" void kernel_launch(void* const* d_in, const int* in_sizes, int n_in,
                              void* d_out, int out_size){
    const float* nxyz  = (const float*)d_in[0];
    const float* cxyz  = (const float*)d_in[1];
    const float* cf_w1 = (const float*)d_in[2];
    const float* cf_b1 = (const float*)d_in[3];
    const float* cf_g  = (const float*)d_in[4];
    const float* cf_be = (const float*)d_in[5];
    const float* cf_w2 = (const float*)d_in[6];
    const float* cf_b2 = (const float*)d_in[7];
    const float* pf_w1 = (const float*)d_in[8];
    const float* pf_b1 = (const float*)d_in[9];
    const float* pf_g  = (const float*)d_in[10];
    const float* pf_be = (const float*)d_in[11];
    const float* pf_w2 = (const float*)d_in[12];
    const float* pf_b2 = (const float*)d_in[13];
    const float* ac_w  = (const float*)d_in[14];
    const float* ac_b  = (const float*)d_in[15];
    const float* ap_w  = (const float*)d_in[16];
    const float* ap_b  = (const float*)d_in[17];
    const float* gamma = (const float*)d_in[18];
    const float* ge_w1 = (const float*)d_in[19];
    const float* ge_b1 = (const float*)d_in[20];
    const float* ge_g  = (const float*)d_in[21];
    const float* ge_be = (const float*)d_in[22];
    const float* ge_w2 = (const float*)d_in[23];
    const float* ge_b2 = (const float*)d_in[24];
    float* out = (float*)d_out;

    cudaFuncSetAttribute(main_kernel, cudaFuncAttributeMaxDynamicSharedMemorySize, MAIN_SMEM);
    cudaFuncSetAttribute(final_kernel, cudaFuncAttributeMaxDynamicSharedMemorySize, FINAL_SMEM);

    zero_kernel<<<1, 64>>>();
    moments_kernel<<<NPTS/256, 256>>>(nxyz, cxyz);
    setup_kernel<<<1, 256>>>(cf_w1, cf_b1, cf_g, cf_be, cf_w2, cf_b2,
                             pf_w1, pf_b1, pf_g, pf_be, pf_w2, pf_b2,
                             ac_w, ac_b, ap_w, ap_b, gamma,
                             ge_w1, ge_b1, ge_w2);
    main_kernel<<<NPTS/128, 256, MAIN_SMEM>>>(nxyz, cxyz);
    bnstats_kernel<<<1, 64>>>(ge_g, ge_be);
    final_kernel<<<NPTS/128, 256, FINAL_SMEM>>>(ge_b2, out);
}

// round 10
// speedup vs baseline: 1.1598x; 1.1598x over previous
#include <cuda_runtime.h>
#include <cuda_bf16.h>
#include <math.h>
#include <stdint.h>

#define BB 8
#define NN 4096
#define KK 16
#define CC 64
#define NPTS (BB*NN*KK)
#define EPSF 1e-6f
#define PI_F 3.14159265358979323846f

// ---------------- device globals ----------------
__device__ double g_mom[34];
__device__ double g_zs1[CC];
__device__ double g_zs2[CC];
__device__ float  g_WcfT[4*CC];
__device__ float  g_bcf[CC];
__device__ float  g_WpfT[5*CC];
__device__ float  g_bpf[CC];
__device__ float  g_Wmain[128*CC];   // [k][c]
__device__ float  g_bz[CC];
__device__ float  g_bp[CC];
__device__ float  g_alpha[CC];
__device__ float  g_beta[CC];
__device__ float  g_z1[CC*NPTS];     // [c][p]
// bf16 split weights [c][k] row-major (contiguous k)
__device__ __nv_bfloat16 g_Whi[CC*128];
__device__ __nv_bfloat16 g_Wlo[CC*128];
__device__ __nv_bfloat16 g_W2hi[CC*CC];
__device__ __nv_bfloat16 g_W2lo[CC*CC];

// ---------------- helpers ----------------
#define MMA_BF16(d0,d1,d2,d3,a0,a1,a2,a3,b0,b1) \
    asm volatile("mma.sync.aligned.m16n8k16.row.col.f32.bf16.bf16.f32 " \
        "{%0,%1,%2,%3}, {%4,%5,%6,%7}, {%8,%9}, {%0,%1,%2,%3};" \
        : "+f"(d0),"+f"(d1),"+f"(d2),"+f"(d3) \
        : "r"(a0),"r"(a1),"r"(a2),"r"(a3),"r"(b0),"r"(b1))

#define LDSM_X4(r0,r1,r2,r3, addr) \
    asm volatile("ldmatrix.sync.aligned.m8n8.x4.shared.b16 {%0,%1,%2,%3}, [%4];" \
        : "=r"(r0),"=r"(r1),"=r"(r2),"=r"(r3) : "r"(addr))

__device__ __forceinline__ uint32_t smem_u32(const void* p){
    uint32_t a;
    asm("{ .reg .u64 t; cvta.to.shared.u64 t, %1; cvt.u32.u64 %0, t; }" : "=r"(a) : "l"(p));
    return a;
}

__device__ __forceinline__ void split2(float v0, float v1, uint32_t& hp, uint32_t& lp){
    __nv_bfloat16 h0 = __float2bfloat16_rn(v0);
    __nv_bfloat16 h1 = __float2bfloat16_rn(v1);
    float r0 = v0 - __bfloat162float(h0);
    float r1 = v1 - __bfloat162float(h1);
    __nv_bfloat16 l0 = __float2bfloat16_rn(r0);
    __nv_bfloat16 l1 = __float2bfloat16_rn(r1);
    hp = (uint32_t)(*(uint16_t*)&h0) | ((uint32_t)(*(uint16_t*)&h1) << 16);
    lp = (uint32_t)(*(uint16_t*)&l0) | ((uint32_t)(*(uint16_t*)&l1) << 16);
}

__device__ __forceinline__ float wsum32(float v){
#pragma unroll
    for (int m=1; m<32; m<<=1) v += __shfl_xor_sync(0xffffffffu, v, m);
    return v;
}
__device__ __forceinline__ float gsum16(float v){
#pragma unroll
    for (int m=1; m<16; m<<=1) v += __shfl_xor_sync(0xffffffffu, v, m);
    return v;
}
__device__ __forceinline__ int clampi(int x,int lo,int hi){return x<lo?lo:(x>hi?hi:x);}

struct Geo { float dx,dy,dz,r,rn,sth,cth,sph,cph,theta; };
__device__ __forceinline__ Geo geom(const float* __restrict__ nxyz,
                                    const float* __restrict__ cxyz, int p){
    int b = p>>16, n = (p>>4)&(NN-1), k = p&(KK-1);
    int cb = (b*3)*NN + n;
    float cx=cxyz[cb], cy=cxyz[cb+NN], cz=cxyz[cb+2*NN];
    int nb = ((b*3)*NN + n)*KK + k;
    Geo g;
    g.dx = nxyz[nb]         - cx;
    g.dy = nxyz[nb+NN*KK]   - cy;
    g.dz = nxyz[nb+2*NN*KK] - cz;
    float r = sqrtf(g.dx*g.dx + g.dy*g.dy + g.dz*g.dz); r = fmaxf(r, EPSF);
    float rho = fmaxf(sqrtf(g.dx*g.dx + g.dy*g.dy), EPSF);
    g.r = r;
    g.theta = atan2f(g.dy, g.dx);
    float phi = atan2f(g.dz, rho);
    float rmean = gsum16(r) * (1.0f/16.0f);
    g.rn = fminf(r/(rmean+EPSF), 3.0f) * (1.0f/3.0f);
    sincosf(g.theta, &g.sth, &g.cth);
    sincosf(phi, &g.sph, &g.cph);
    return g;
}
struct Mix { float c0,c1,c2,c3, m0,m1,m2,m3, s_k; };
__device__ __forceinline__ Mix make_mix(const Geo& g){
    float ridx = g.rn*(2.0f - 1e-6f);
    float aidx = ((g.theta + PI_F)*(0.5f/PI_F))*(12.0f - 1e-6f);
    float ri0f = floorf(ridx); float rw1 = ridx-ri0f, rw0 = 1.0f-rw1;
    int ri0 = clampi((int)ri0f,0,1), ri1 = clampi((int)ri0f+1,0,1);
    float ai0f = floorf(aidx); float aw1 = aidx-ai0f, aw0 = 1.0f-aw1;
    int ai0 = clampi((int)ai0f,0,11), ai1 = clampi((int)ai0f+1,0,11);
    float w00=rw0*aw0, w01=rw0*aw1, w10=rw1*aw0, w11=rw1*aw1;
    int c00=ri0*12+ai0, c01=ri0*12+ai1, c10=ri1*12+ai0, c11=ri1*12+ai1;
    int t0 = __shfl_sync(0xffffffffu, c00, 0, 16);
    int t1 = __shfl_sync(0xffffffffu, c01, 0, 16);
    int t2 = __shfl_sync(0xffffffffu, c10, 0, 16);
    int t3 = __shfl_sync(0xffffffffu, c11, 0, 16);
    Mix mx;
    mx.c0 = (c00==t0?w00:0.f)+(c01==t0?w01:0.f)+(c10==t0?w10:0.f)+(c11==t0?w11:0.f);
    mx.c1 = (c00==t1?w00:0.f)+(c01==t1?w01:0.f)+(c10==t1?w10:0.f)+(c11==t1?w11:0.f);
    mx.c2 = (c00==t2?w00:0.f)+(c01==t2?w01:0.f)+(c10==t2?w10:0.f)+(c11==t2?w11:0.f);
    mx.c3 = (c00==t3?w00:0.f)+(c01==t3?w01:0.f)+(c10==t3?w10:0.f)+(c11==t3?w11:0.f);
    float den0 = gsum16(mx.c0), den1 = gsum16(mx.c1);
    float den2 = gsum16(mx.c2), den3 = gsum16(mx.c3);
    mx.m0 = w00/fmaxf(den0,EPSF); mx.m1 = w01/fmaxf(den1,EPSF);
    mx.m2 = w10/fmaxf(den2,EPSF); mx.m3 = w11/fmaxf(den3,EPSF);
    mx.s_k = mx.m0*den0 + mx.m1*den1 + mx.m2*den2 + mx.m3*den3;
    return mx;
}

// ---------------- small kernels ----------------
__global__ void zero_kernel(){
    int t = threadIdx.x;
    if (t < 34) g_mom[t] = 0.0;
    if (t < CC) { g_zs1[t]=0.0; g_zs2[t]=0.0; }
}

__global__ __launch_bounds__(256) void moments_kernel(const float* __restrict__ nxyz,
                                                      const float* __restrict__ cxyz){
    __shared__ double smom[34];
    int tid = threadIdx.x;
    if (tid < 34) smom[tid] = 0.0;
    __syncthreads();
    int p = blockIdx.x*256 + tid;
    Geo g = geom(nxyz, cxyz, p);
    float fc[4] = {g.dx, g.dy, g.dz, g.r};
    float fp[5] = {g.rn, g.sth, g.cth, g.sph, g.cph};
    float v[34];
#pragma unroll
    for (int i=0;i<4;i++){
        v[i] = fc[i];
#pragma unroll
        for (int j=i;j<4;j++) v[4 + i*4 - (i*(i-1))/2 + (j-i)] = fc[i]*fc[j];
    }
#pragma unroll
    for (int i=0;i<5;i++){
        v[14+i] = fp[i];
#pragma unroll
        for (int j=i;j<5;j++) v[19 + i*5 - (i*(i-1))/2 + (j-i)] = fp[i]*fp[j];
    }
#pragma unroll
    for (int i=0;i<34;i++){
        float s = wsum32(v[i]);
        if ((tid&31)==0) atomicAdd(&smom[i], (double)s);
    }
    __syncthreads();
    if (tid < 34) atomicAdd(&g_mom[tid], smom[tid]);
}

__global__ void setup_kernel(
    const float* __restrict__ cf_w1, const float* __restrict__ cf_b1,
    const float* __restrict__ cf_g,  const float* __restrict__ cf_be,
    const float* __restrict__ cf_w2, const float* __restrict__ cf_b2,
    const float* __restrict__ pf_w1, const float* __restrict__ pf_b1,
    const float* __restrict__ pf_g,  const float* __restrict__ pf_be,
    const float* __restrict__ pf_w2, const float* __restrict__ pf_b2,
    const float* __restrict__ ac_w,  const float* __restrict__ ac_b,
    const float* __restrict__ ap_w,  const float* __restrict__ ap_b,
    const float* __restrict__ gamma_p,
    const float* __restrict__ ge_w1, const float* __restrict__ ge_b1,
    const float* __restrict__ ge_w2)
{
    __shared__ float sT[CC*CC];
    __shared__ float sv1[CC], sv2[CC];
    int tid = threadIdx.x;
    float gam = gamma_p[0];
    const double inv = 1.0/(double)NPTS;

    if (tid < CC){
        { // cart BN fold
            double mu[4], cov[4][4];
#pragma unroll
            for (int i=0;i<4;i++) mu[i] = g_mom[i]*inv;
#pragma unroll
            for (int i=0;i<4;i++)
#pragma unroll
                for (int j=i;j<4;j++){
                    double c2 = g_mom[4 + i*4 - (i*(i-1))/2 + (j-i)]*inv - mu[i]*mu[j];
                    cov[i][j]=c2; cov[j][i]=c2;
                }
            double w[4], m=(double)cf_b1[tid], vv=0.0;
#pragma unroll
            for (int i=0;i<4;i++){ w[i]=(double)cf_w1[tid*4+i]; m += w[i]*mu[i]; }
#pragma unroll
            for (int i=0;i<4;i++)
#pragma unroll
                for (int j=0;j<4;j++) vv += w[i]*w[j]*cov[i][j];
            double al = (double)cf_g[tid]/sqrt(vv+1e-5);
#pragma unroll
            for (int i=0;i<4;i++) g_WcfT[i*CC+tid] = (float)(w[i]*al);
            g_bcf[tid] = (float)(((double)cf_b1[tid]-m)*al + (double)cf_be[tid]);
        }
        { // polar BN fold
            double mu[5], cov[5][5];
#pragma unroll
            for (int i=0;i<5;i++) mu[i] = g_mom[14+i]*inv;
#pragma unroll
            for (int i=0;i<5;i++)
#pragma unroll
                for (int j=i;j<5;j++){
                    double c2 = g_mom[19 + i*5 - (i*(i-1))/2 + (j-i)]*inv - mu[i]*mu[j];
                    cov[i][j]=c2; cov[j][i]=c2;
                }
            double w[5], m=(double)pf_b1[tid], vv=0.0;
#pragma unroll
            for (int i=0;i<5;i++){ w[i]=(double)pf_w1[tid*5+i]; m += w[i]*mu[i]; }
#pragma unroll
            for (int i=0;i<5;i++)
#pragma unroll
                for (int j=0;j<5;j++) vv += w[i]*w[j]*cov[i][j];
            double al = (double)pf_g[tid]/sqrt(vv+1e-5);
#pragma unroll
            for (int i=0;i<5;i++) g_WpfT[i*CC+tid] = (float)(w[i]*al);
            g_bpf[tid] = (float)(((double)pf_b1[tid]-m)*al + (double)pf_be[tid]);
        }
    }
    for (int e=tid;e<CC*CC;e+=blockDim.x){
        int m=e>>6, j=e&63; float s=0.f;
        for (int l=0;l<CC;l++) s += ac_w[m*CC+l]*cf_w2[l*CC+j];
        sT[e]=s;
    }
    __syncthreads();
    for (int e=tid;e<CC*CC;e+=blockDim.x){
        int c=e>>6, j=e&63; float s=0.f;
        for (int m=0;m<CC;m++) s += ge_w1[c*CC+m]*sT[m*CC+j];
        g_Wmain[j*CC+c]=s;
    }
    __syncthreads();
    for (int e=tid;e<CC*CC;e+=blockDim.x){
        int m=e>>6, j=e&63; float s=0.f;
        for (int l=0;l<CC;l++) s += ap_w[m*CC+l]*pf_w2[l*CC+j];
        sT[e]=s;
    }
    __syncthreads();
    for (int e=tid;e<CC*CC;e+=blockDim.x){
        int c=e>>6, j=e&63; float s=0.f;
        for (int m=0;m<CC;m++) s += ge_w1[c*CC+m]*sT[m*CC+j];
        g_Wmain[(64+j)*CC+c]=gam*s;
    }
    if (tid < CC){
        float s1 = ac_b[tid] + gam*ap_b[tid];
        for (int j=0;j<CC;j++) s1 += ac_w[tid*CC+j]*cf_b2[j];
        sv1[tid]=s1;
        float s2 = 0.f;
        for (int j=0;j<CC;j++) s2 += ap_w[tid*CC+j]*pf_b2[j];
        sv2[tid]=s2;
    }
    __syncthreads();
    if (tid < CC){
        float bz = ge_b1[tid], bp = 0.f;
        for (int m=0;m<CC;m++){ bz += ge_w1[tid*CC+m]*sv1[m]; bp += ge_w1[tid*CC+m]*sv2[m]; }
        g_bz[tid]=bz; g_bp[tid]=gam*bp;
    }
    __syncthreads();
    for (int e=tid; e<CC*128; e+=blockDim.x){
        int k = e & 127, c = e >> 7;
        float v = g_Wmain[k*CC + c];
        __nv_bfloat16 h = __float2bfloat16_rn(v);
        float rem = v - __bfloat162float(h);
        g_Whi[c*128 + k] = h;
        g_Wlo[c*128 + k] = __float2bfloat16_rn(rem);
    }
    for (int e=tid; e<CC*CC; e+=blockDim.x){
        int j = e & 63, c = e >> 6;
        float v = ge_w2[c*CC + j];
        __nv_bfloat16 h = __float2bfloat16_rn(v);
        float rem = v - __bfloat162float(h);
        g_W2hi[c*64 + j] = h;
        g_W2lo[c*64 + j] = __float2bfloat16_rn(rem);
    }
}

// ---------------- main kernel smem layout (bytes) ----------------
// W tiles OVERLAY the HP/GEO scratch (disjoint lifetimes) -> total 114944,
// small enough for 2 CTAs/SM (measured 24.5% occ at this size in R7).
#define HSTR 136   // 272B row stride; 68 words == 4 mod 32 -> conflict-free LDSM
#define WSTR 136
#define SH_HHI   0          // 34816
#define SH_HLO   34816      // -> 69632
// scratch union [69632 .. 107008):
#define SH_HP    69632      // fp32 Hp 32768 -> 102400   (phases B..convert)
#define SH_GEO   102400     // 4608 -> 107008            (phase A..B)
#define SH_WHI   69632      // 17408 -> 87040            (GEMM phase, overlays HP)
#define SH_WLO   87040      // 17408 -> 104448           (GEMM phase, overlays HP/GEO)
#define SH_CC    107008     // 2048 (coefs; reused as stats S1)
#define SH_MM    109056     // 2048 (coefs; reused as stats S2)
#define SH_SK    111104     // 512
#define SH_WCF   111616     // 1024
#define SH_WPF   112640     // 1280
#define SH_BCF   113920     // 256
#define SH_BPF   114176     // 256
#define SH_BZ    114432     // 256
#define SH_BP    114688     // 256
#define MAIN_SMEM 114944

__global__ __launch_bounds__(256,2) void main_kernel(const float* __restrict__ nxyz,
                                                     const float* __restrict__ cxyz){
    extern __shared__ char smc[];
    float* sHPf = (float*)(smc + SH_HP);
    float* sGEO = (float*)(smc + SH_GEO);
    float* sCc  = (float*)(smc + SH_CC);
    float* sMm  = (float*)(smc + SH_MM);
    float* sSK  = (float*)(smc + SH_SK);
    float* sWcf = (float*)(smc + SH_WCF);
    float* sWpf = (float*)(smc + SH_WPF);
    float* sbcf = (float*)(smc + SH_BCF);
    float* sbpf = (float*)(smc + SH_BPF);
    float* sbz  = (float*)(smc + SH_BZ);
    float* sbp  = (float*)(smc + SH_BP);
    int tid = threadIdx.x;
    int wid = tid >> 5;
    int lane = tid & 31;

    for (int i=tid;i<4*CC;i+=256) sWcf[i]=g_WcfT[i];
    for (int i=tid;i<5*CC;i+=256) sWpf[i]=g_WpfT[i];
    if (tid < CC){
        sbcf[tid]=g_bcf[tid]; sbpf[tid]=g_bpf[tid];
        sbz[tid]=g_bz[tid];   sbp[tid]=g_bp[tid];
    }
    __syncthreads();

    int p0 = blockIdx.x*128;

    // phase A: geometry + mix coeffs (threads 0-127)
    if (tid < 128){
        Geo g = geom(nxyz, cxyz, p0 + tid);
        Mix mx = make_mix(g);
        sGEO[0*128+tid]=g.dx;  sGEO[1*128+tid]=g.dy;  sGEO[2*128+tid]=g.dz;
        sGEO[3*128+tid]=g.r;   sGEO[4*128+tid]=g.rn;  sGEO[5*128+tid]=g.sth;
        sGEO[6*128+tid]=g.cth; sGEO[7*128+tid]=g.sph; sGEO[8*128+tid]=g.cph;
        sCc[0*128+tid]=mx.c0; sCc[1*128+tid]=mx.c1; sCc[2*128+tid]=mx.c2; sCc[3*128+tid]=mx.c3;
        sMm[0*128+tid]=mx.m0; sMm[1*128+tid]=mx.m1; sMm[2*128+tid]=mx.m2; sMm[3*128+tid]=mx.m3;
        sSK[tid]=mx.s_k;
    }
    __syncthreads();

    // phase B: first layers
    {
        int m = tid & 127;
        int jh = (tid >> 7) * 32;
        float dx=sGEO[m],     dy=sGEO[128+m], dz=sGEO[256+m], r =sGEO[384+m];
        float rn=sGEO[512+m], st=sGEO[640+m], ct=sGEO[768+m];
        float sp=sGEO[896+m], cp=sGEO[1024+m];
        char* Hhi = smc + SH_HHI;
        char* Hlo = smc + SH_HLO;
#pragma unroll 4
        for (int j=jh; j<jh+32; j+=2){
            float h0 = sbcf[j];
            h0 = fmaf(dx,sWcf[j],h0); h0 = fmaf(dy,sWcf[64+j],h0);
            h0 = fmaf(dz,sWcf[128+j],h0); h0 = fmaf(r,sWcf[192+j],h0);
            h0 = fmaxf(h0,0.f);
            float h1 = sbcf[j+1];
            h1 = fmaf(dx,sWcf[j+1],h1); h1 = fmaf(dy,sWcf[64+j+1],h1);
            h1 = fmaf(dz,sWcf[128+j+1],h1); h1 = fmaf(r,sWcf[192+j+1],h1);
            h1 = fmaxf(h1,0.f);
            uint32_t hp, lp; split2(h0, h1, hp, lp);
            uint32_t off = (uint32_t)(m*HSTR + j)*2;
            *(uint32_t*)(Hhi + off) = hp;
            *(uint32_t*)(Hlo + off) = lp;
            float q0 = sbpf[j];
            q0 = fmaf(rn,sWpf[j],q0); q0 = fmaf(st,sWpf[64+j],q0);
            q0 = fmaf(ct,sWpf[128+j],q0); q0 = fmaf(sp,sWpf[192+j],q0);
            q0 = fmaf(cp,sWpf[256+j],q0);
            sHPf[j*128+m] = fmaxf(q0,0.f);
            float q1 = sbpf[j+1];
            q1 = fmaf(rn,sWpf[j+1],q1); q1 = fmaf(st,sWpf[64+j+1],q1);
            q1 = fmaf(ct,sWpf[128+j+1],q1); q1 = fmaf(sp,sWpf[192+j+1],q1);
            q1 = fmaf(cp,sWpf[256+j+1],q1);
            sHPf[(j+1)*128+m] = fmaxf(q1,0.f);
        }
    }
    __syncthreads();

    // mix: 512 tasks
#pragma unroll
    for (int t2i=0;t2i<2;t2i++){
        int tk = t2i*256 + tid;
        int j = tk>>3, grp = tk&7;
        float* hrow = sHPf + j*128 + grp*16;
        const float* cb = sCc + grp*16;
        const float* mb = sMm + grp*16;
        float h[16];
#pragma unroll
        for (int k=0;k<16;k++) h[k]=hrow[k];
        float g0=0.f,g1=0.f,g2=0.f,g3=0.f;
#pragma unroll
        for (int k=0;k<16;k++){
            g0 = fmaf(cb[0*128+k], h[k], g0);
            g1 = fmaf(cb[1*128+k], h[k], g1);
            g2 = fmaf(cb[2*128+k], h[k], g2);
            g3 = fmaf(cb[3*128+k], h[k], g3);
        }
#pragma unroll
        for (int k=0;k<16;k++){
            float o = mb[0*128+k]*g0;
            o = fmaf(mb[1*128+k], g1, o);
            o = fmaf(mb[2*128+k], g2, o);
            o = fmaf(mb[3*128+k], g3, o);
            hrow[k] = o;
        }
    }
    __syncthreads();

    // convert polar to bf16 H cols 64..127; zero stats staging
    {
        int m = tid & 127;
        int ch = (tid >> 7) * 32;
        char* Hhi = smc + SH_HHI;
        char* Hlo = smc + SH_HLO;
#pragma unroll 4
        for (int jj=ch; jj<ch+32; jj+=2){
            float v0 = sHPf[jj*128+m];
            float v1 = sHPf[(jj+1)*128+m];
            uint32_t hp, lp; split2(v0, v1, hp, lp);
            uint32_t off = (uint32_t)(m*HSTR + 64 + jj)*2;
            *(uint32_t*)(Hhi + off) = hp;
            *(uint32_t*)(Hlo + off) = lp;
        }
    }
    __syncthreads();   // HP/GEO scratch now dead -> W tiles can overlay

    // copy W tiles into (overlaid) smem, padded stride for LDSM
    {
        int c = tid >> 2, q = tid & 3;
        const uint4* gh = (const uint4*)(g_Whi + c*128 + q*32);
        const uint4* gl = (const uint4*)(g_Wlo + c*128 + q*32);
        uint4* shh = (uint4*)(smc + SH_WHI + (c*WSTR + q*32)*2);
        uint4* shl = (uint4*)(smc + SH_WLO + (c*WSTR + q*32)*2);
#pragma unroll
        for (int i=0;i<4;i++){ shh[i]=gh[i]; shl[i]=gl[i]; }
    }
    if (tid < CC){ sCc[tid]=0.f; sMm[tid]=0.f; }
    __syncthreads();

    // GEMM via mma.sync bf16, ldmatrix fragment feeds
    {
        int g = lane >> 2;
        int t2 = (lane & 3) * 2;
        int c0 = (wid & 3) * 16;
        int ph = (wid >> 2) * 64;
        int r0 = c0 + g, r1 = c0 + g + 8;
        int lrow = lane & 7, lgrp = lane >> 3;

        uint32_t Ah[8][4], Al[8][4];
        {
            uint32_t arow = (uint32_t)(c0 + (lgrp & 1)*8 + lrow);
            uint32_t acol = (uint32_t)((lgrp >> 1) * 8);
            uint32_t bh = smem_u32(smc + SH_WHI) + (arow*WSTR + acol)*2;
            uint32_t bl = smem_u32(smc + SH_WLO) + (arow*WSTR + acol)*2;
#pragma unroll
            for (int ks=0; ks<8; ks++){
                LDSM_X4(Ah[ks][0],Ah[ks][1],Ah[ks][2],Ah[ks][3], bh + ks*32);
                LDSM_X4(Al[ks][0],Al[ks][1],Al[ks][2],Al[ks][3], bl + ks*32);
            }
        }
        uint32_t hbase = smem_u32(smc + SH_HHI);
        uint32_t lbase = smem_u32(smc + SH_HLO);
        float bz0 = sbz[r0], bz1 = sbz[r1], bp0 = sbp[r0], bp1 = sbp[r1];
        float s10=0.f, s20=0.f, s11=0.f, s21=0.f;
#pragma unroll 1
        for (int nt=0; nt<8; nt++){
            int pn = ph + nt*8;
            uint32_t badh = hbase + (uint32_t)((pn + lrow)*HSTR + lgrp*8)*2;
            uint32_t badl = lbase + (uint32_t)((pn + lrow)*HSTR + lgrp*8)*2;
            uint32_t Bh[16], Bl[16];
#pragma unroll
            for (int kq=0; kq<4; kq++){
                LDSM_X4(Bh[kq*4+0],Bh[kq*4+1],Bh[kq*4+2],Bh[kq*4+3], badh + kq*64);
                LDSM_X4(Bl[kq*4+0],Bl[kq*4+1],Bl[kq*4+2],Bl[kq*4+3], badl + kq*64);
            }
            float a0=0.f, a1=0.f, a2=0.f, a3=0.f;
#pragma unroll
            for (int ks=0; ks<8; ks++){
                uint32_t bh0 = Bh[2*ks], bh1 = Bh[2*ks+1];
                uint32_t bl0 = Bl[2*ks], bl1 = Bl[2*ks+1];
                MMA_BF16(a0,a1,a2,a3, Ah[ks][0],Ah[ks][1],Ah[ks][2],Ah[ks][3], bh0,bh1);
                MMA_BF16(a0,a1,a2,a3, Ah[ks][0],Ah[ks][1],Ah[ks][2],Ah[ks][3], bl0,bl1);
                MMA_BF16(a0,a1,a2,a3, Al[ks][0],Al[ks][1],Al[ks][2],Al[ks][3], bh0,bh1);
            }
            int col = pn + t2;
            float sk0 = sSK[col], sk1 = sSK[col+1];
            float z00 = a0 + fmaf(bp0, sk0, bz0);
            float z01 = a1 + fmaf(bp0, sk1, bz0);
            float z10 = a2 + fmaf(bp1, sk0, bz1);
            float z11 = a3 + fmaf(bp1, sk1, bz1);
            *(float2*)(g_z1 + (size_t)r0*NPTS + p0 + col) = make_float2(z00,z01);
            *(float2*)(g_z1 + (size_t)r1*NPTS + p0 + col) = make_float2(z10,z11);
            s10 += z00+z01; s20 += z00*z00+z01*z01;
            s11 += z10+z11; s21 += z10*z10+z11*z11;
        }
        s10 += __shfl_xor_sync(0xffffffffu, s10, 1); s10 += __shfl_xor_sync(0xffffffffu, s10, 2);
        s20 += __shfl_xor_sync(0xffffffffu, s20, 1); s20 += __shfl_xor_sync(0xffffffffu, s20, 2);
        s11 += __shfl_xor_sync(0xffffffffu, s11, 1); s11 += __shfl_xor_sync(0xffffffffu, s11, 2);
        s21 += __shfl_xor_sync(0xffffffffu, s21, 1); s21 += __shfl_xor_sync(0xffffffffu, s21, 2);
        if ((lane & 3) == 0){
            atomicAdd(&sCc[r0], s10); atomicAdd(&sMm[r0], s20);
            atomicAdd(&sCc[r1], s11); atomicAdd(&sMm[r1], s21);
        }
    }
    __syncthreads();
    if (tid < CC){
        atomicAdd(&g_zs1[tid], (double)sCc[tid]);
        atomicAdd(&g_zs2[tid], (double)sMm[tid]);
    }
}

__global__ void bnstats_kernel(const float* __restrict__ ge_g, const float* __restrict__ ge_be){
    int c = threadIdx.x;
    if (c < CC){
        double mean = g_zs1[c]/(double)NPTS;
        double var  = g_zs2[c]/(double)NPTS - mean*mean;
        double a = (double)ge_g[c]/sqrt(var + 1e-5);
        g_alpha[c] = (float)a;
        g_beta[c]  = (float)((double)ge_be[c] - mean*a);
    }
}

// ---------------- final kernel ----------------
#define FSTR 72    // 144B stride; 36 words == 4 mod 32 -> conflict-free LDSM
#define F2STR 72
#define FH_HHI 0        // 18432
#define FH_HLO 18432    // -> 36864
#define FH_WHI 36864    // 9216 -> 46080
#define FH_WLO 46080    // -> 55296
#define FH_A   55296    // 256
#define FH_BV  55552    // 256
#define FH_B2  55808    // 256
#define FINAL_SMEM 56064

__global__ __launch_bounds__(256,2) void final_kernel(const float* __restrict__ ge_b2,
                                                      float* __restrict__ out){
    extern __shared__ char smc[];
    float* sa  = (float*)(smc + FH_A);
    float* sbv = (float*)(smc + FH_BV);
    float* sb2 = (float*)(smc + FH_B2);
    int tid = threadIdx.x;
    int wid = tid >> 5;
    int lane = tid & 31;

    {
        int c = tid >> 2, q = tid & 3;
        const uint4* gh = (const uint4*)(g_W2hi + c*64 + q*16);
        const uint4* gl = (const uint4*)(g_W2lo + c*64 + q*16);
        uint4* shh = (uint4*)(smc + FH_WHI + (c*F2STR + q*16)*2);
        uint4* shl = (uint4*)(smc + FH_WLO + (c*F2STR + q*16)*2);
#pragma unroll
        for (int i=0;i<2;i++){ shh[i]=gh[i]; shl[i]=gl[i]; }
    }
    if (tid < CC){ sa[tid]=g_alpha[tid]; sbv[tid]=g_beta[tid]; sb2[tid]=ge_b2[tid]; }
    __syncthreads();

    int p0 = blockIdx.x*128;

    {
        int m = tid & 127;
        int ch = (tid >> 7) * 32;
        char* Hhi = smc + FH_HHI;
        char* Hlo = smc + FH_HLO;
#pragma unroll 4
        for (int c=ch; c<ch+32; c+=2){
            float z0 = g_z1[(size_t)c*NPTS + p0 + m];
            float z1v = g_z1[(size_t)(c+1)*NPTS + p0 + m];
            float h0 = fmaxf(fmaf(z0, sa[c], sbv[c]), 0.f);
            float h1 = fmaxf(fmaf(z1v, sa[c+1], sbv[c+1]), 0.f);
            uint32_t hp, lp; split2(h0, h1, hp, lp);
            uint32_t off = (uint32_t)(m*FSTR + c)*2;
            *(uint32_t*)(Hhi + off) = hp;
            *(uint32_t*)(Hlo + off) = lp;
        }
    }
    __syncthreads();

    {
        int g = lane >> 2;
        int t2 = (lane & 3) * 2;
        int c0 = (wid & 3) * 16;
        int ph = (wid >> 2) * 64;
        int r0 = c0 + g, r1 = c0 + g + 8;
        int lrow = lane & 7, lgrp = lane >> 3;

        uint32_t Ah[4][4], Al[4][4];
        {
            uint32_t arow = (uint32_t)(c0 + (lgrp & 1)*8 + lrow);
            uint32_t acol = (uint32_t)((lgrp >> 1) * 8);
            uint32_t bh = smem_u32(smc + FH_WHI) + (arow*F2STR + acol)*2;
            uint32_t bl = smem_u32(smc + FH_WLO) + (arow*F2STR + acol)*2;
#pragma unroll
            for (int ks=0; ks<4; ks++){
                LDSM_X4(Ah[ks][0],Ah[ks][1],Ah[ks][2],Ah[ks][3], bh + ks*32);
                LDSM_X4(Al[ks][0],Al[ks][1],Al[ks][2],Al[ks][3], bl + ks*32);
            }
        }
        uint32_t hbase = smem_u32(smc + FH_HHI);
        uint32_t lbase = smem_u32(smc + FH_HLO);
        float b0v = sb2[r0], b1v = sb2[r1];
        int b = p0 >> 16;
        int nk0 = p0 & 65535;
        float* ob = out + (size_t)b*CC*65536;
#pragma unroll 1
        for (int nt=0; nt<8; nt++){
            int pn = ph + nt*8;
            uint32_t badh = hbase + (uint32_t)((pn + lrow)*FSTR + lgrp*8)*2;
            uint32_t badl = lbase + (uint32_t)((pn + lrow)*FSTR + lgrp*8)*2;
            uint32_t Bh[8], Bl[8];
#pragma unroll
            for (int kq=0; kq<2; kq++){
                LDSM_X4(Bh[kq*4+0],Bh[kq*4+1],Bh[kq*4+2],Bh[kq*4+3], badh + kq*64);
                LDSM_X4(Bl[kq*4+0],Bl[kq*4+1],Bl[kq*4+2],Bl[kq*4+3], badl + kq*64);
            }
            float a0=0.f, a1=0.f, a2=0.f, a3=0.f;
#pragma unroll
            for (int ks=0; ks<4; ks++){
                uint32_t bh0 = Bh[2*ks], bh1 = Bh[2*ks+1];
                uint32_t bl0 = Bl[2*ks], bl1 = Bl[2*ks+1];
                MMA_BF16(a0,a1,a2,a3, Ah[ks][0],Ah[ks][1],Ah[ks][2],Ah[ks][3], bh0,bh1);
                MMA_BF16(a0,a1,a2,a3, Ah[ks][0],Ah[ks][1],Ah[ks][2],Ah[ks][3], bl0,bl1);
                MMA_BF16(a0,a1,a2,a3, Al[ks][0],Al[ks][1],Al[ks][2],Al[ks][3], bh0,bh1);
            }
            int col = pn + t2;
            *(float2*)(ob + (size_t)r0*65536 + nk0 + col) = make_float2(a0+b0v, a1+b0v);
            *(float2*)(ob + (size_t)r1*65536 + nk0 + col) = make_float2(a2+b1v, a3+b1v);
        }
    }
}

extern "C" void kernel_launch(void* const* d_in, const int* in_sizes, int n_in,
                              void* d_out, int out_size){
    const float* nxyz  = (const float*)d_in[0];
    const float* cxyz  = (const float*)d_in[1];
    const float* cf_w1 = (const float*)d_in[2];
    const float* cf_b1 = (const float*)d_in[3];
    const float* cf_g  = (const float*)d_in[4];
    const float* cf_be = (const float*)d_in[5];
    const float* cf_w2 = (const float*)d_in[6];
    const float* cf_b2 = (const float*)d_in[7];
    const float* pf_w1 = (const float*)d_in[8];
    const float* pf_b1 = (const float*)d_in[9];
    const float* pf_g  = (const float*)d_in[10];
    const float* pf_be = (const float*)d_in[11];
    const float* pf_w2 = (const float*)d_in[12];
    const float* pf_b2 = (const float*)d_in[13];
    const float* ac_w  = (const float*)d_in[14];
    const float* ac_b  = (const float*)d_in[15];
    const float* ap_w  = (const float*)d_in[16];
    const float* ap_b  = (const float*)d_in[17];
    const float* gamma = (const float*)d_in[18];
    const float* ge_w1 = (const float*)d_in[19];
    const float* ge_b1 = (const float*)d_in[20];
    const float* ge_g  = (const float*)d_in[21];
    const float* ge_be = (const float*)d_in[22];
    const float* ge_w2 = (const float*)d_in[23];
    const float* ge_b2 = (const float*)d_in[24];
    float* out = (float*)d_out;

    cudaFuncSetAttribute(main_kernel, cudaFuncAttributeMaxDynamicSharedMemorySize, MAIN_SMEM);
    cudaFuncSetAttribute(final_kernel, cudaFuncAttributeMaxDynamicSharedMemorySize, FINAL_SMEM);

    zero_kernel<<<1, 64>>>();
    moments_kernel<<<NPTS/256, 256>>>(nxyz, cxyz);
    setup_kernel<<<1, 256>>>(cf_w1, cf_b1, cf_g, cf_be, cf_w2, cf_b2,
                             pf_w1, pf_b1, pf_g, pf_be, pf_w2, pf_b2,
                             ac_w, ac_b, ap_w, ap_b, gamma,
                             ge_w1, ge_b1, ge_w2);
    main_kernel<<<NPTS/128, 256, MAIN_SMEM>>>(nxyz, cxyz);
    bnstats_kernel<<<1, 64>>>(ge_g, ge_be);
    final_kernel<<<NPTS/128, 256, FINAL_SMEM>>>(ge_b2, out);
}

// round 11
// speedup vs baseline: 1.3876x; 1.1964x over previous
#include <cuda_runtime.h>
#include <cuda_bf16.h>
#include <math.h>
#include <stdint.h>

#define BB 8
#define NN 4096
#define KK 16
#define CC 64
#define NPTS (BB*NN*KK)
#define EPSF 1e-6f
#define PI_F 3.14159265358979323846f

// ---------------- device globals ----------------
__device__ double g_mom[34];
__device__ double g_zs1[CC];
__device__ double g_zs2[CC];
__device__ float  g_WcfT[4*CC];
__device__ float  g_bcf[CC];
__device__ float  g_WpfT[5*CC];
__device__ float  g_bpf[CC];
__device__ float  g_Wmain[128*CC];   // [k][c]
__device__ float  g_bz[CC];
__device__ float  g_bp[CC];
__device__ float  g_alpha[CC];
__device__ float  g_beta[CC];
__device__ float  g_z1[CC*NPTS];     // [c][p]
// bf16 split weights [c][k] row-major (contiguous k)
__device__ __nv_bfloat16 g_Whi[CC*128];
__device__ __nv_bfloat16 g_Wlo[CC*128];
__device__ __nv_bfloat16 g_W2hi[CC*CC];
__device__ __nv_bfloat16 g_W2lo[CC*CC];

// ---------------- helpers ----------------
#define MMA_BF16(d0,d1,d2,d3,a0,a1,a2,a3,b0,b1) \
    asm volatile("mma.sync.aligned.m16n8k16.row.col.f32.bf16.bf16.f32 " \
        "{%0,%1,%2,%3}, {%4,%5,%6,%7}, {%8,%9}, {%0,%1,%2,%3};" \
        : "+f"(d0),"+f"(d1),"+f"(d2),"+f"(d3) \
        : "r"(a0),"r"(a1),"r"(a2),"r"(a3),"r"(b0),"r"(b1))

#define LDSM_X4(r0,r1,r2,r3, addr) \
    asm volatile("ldmatrix.sync.aligned.m8n8.x4.shared.b16 {%0,%1,%2,%3}, [%4];" \
        : "=r"(r0),"=r"(r1),"=r"(r2),"=r"(r3) : "r"(addr))

__device__ __forceinline__ uint32_t smem_u32(const void* p){
    uint32_t a;
    asm("{ .reg .u64 t; cvta.to.shared.u64 t, %1; cvt.u32.u64 %0, t; }" : "=r"(a) : "l"(p));
    return a;
}

__device__ __forceinline__ uint32_t pack_bf(float v0, float v1){
    __nv_bfloat16 h0 = __float2bfloat16_rn(v0);
    __nv_bfloat16 h1 = __float2bfloat16_rn(v1);
    return (uint32_t)(*(uint16_t*)&h0) | ((uint32_t)(*(uint16_t*)&h1) << 16);
}
__device__ __forceinline__ void split2(float v0, float v1, uint32_t& hp, uint32_t& lp){
    __nv_bfloat16 h0 = __float2bfloat16_rn(v0);
    __nv_bfloat16 h1 = __float2bfloat16_rn(v1);
    float r0 = v0 - __bfloat162float(h0);
    float r1 = v1 - __bfloat162float(h1);
    hp = (uint32_t)(*(uint16_t*)&h0) | ((uint32_t)(*(uint16_t*)&h1) << 16);
    lp = pack_bf(r0, r1);
}

__device__ __forceinline__ float wsum32(float v){
#pragma unroll
    for (int m=1; m<32; m<<=1) v += __shfl_xor_sync(0xffffffffu, v, m);
    return v;
}
__device__ __forceinline__ float gsum16(float v){
#pragma unroll
    for (int m=1; m<16; m<<=1) v += __shfl_xor_sync(0xffffffffu, v, m);
    return v;
}
__device__ __forceinline__ int clampi(int x,int lo,int hi){return x<lo?lo:(x>hi?hi:x);}

struct Geo { float dx,dy,dz,r,rn,sth,cth,sph,cph,theta; };
__device__ __forceinline__ Geo geom(const float* __restrict__ nxyz,
                                    const float* __restrict__ cxyz, int p){
    int b = p>>16, n = (p>>4)&(NN-1), k = p&(KK-1);
    int cb = (b*3)*NN + n;
    float cx=cxyz[cb], cy=cxyz[cb+NN], cz=cxyz[cb+2*NN];
    int nb = ((b*3)*NN + n)*KK + k;
    Geo g;
    g.dx = nxyz[nb]         - cx;
    g.dy = nxyz[nb+NN*KK]   - cy;
    g.dz = nxyz[nb+2*NN*KK] - cz;
    float r = sqrtf(g.dx*g.dx + g.dy*g.dy + g.dz*g.dz); r = fmaxf(r, EPSF);
    float rho = fmaxf(sqrtf(g.dx*g.dx + g.dy*g.dy), EPSF);
    g.r = r;
    g.theta = atan2f(g.dy, g.dx);
    float phi = atan2f(g.dz, rho);
    float rmean = gsum16(r) * (1.0f/16.0f);
    g.rn = fminf(r/(rmean+EPSF), 3.0f) * (1.0f/3.0f);
    sincosf(g.theta, &g.sth, &g.cth);
    sincosf(phi, &g.sph, &g.cph);
    return g;
}
struct Mix { float c0,c1,c2,c3, m0,m1,m2,m3, s_k; };
__device__ __forceinline__ Mix make_mix(const Geo& g){
    float ridx = g.rn*(2.0f - 1e-6f);
    float aidx = ((g.theta + PI_F)*(0.5f/PI_F))*(12.0f - 1e-6f);
    float ri0f = floorf(ridx); float rw1 = ridx-ri0f, rw0 = 1.0f-rw1;
    int ri0 = clampi((int)ri0f,0,1), ri1 = clampi((int)ri0f+1,0,1);
    float ai0f = floorf(aidx); float aw1 = aidx-ai0f, aw0 = 1.0f-aw1;
    int ai0 = clampi((int)ai0f,0,11), ai1 = clampi((int)ai0f+1,0,11);
    float w00=rw0*aw0, w01=rw0*aw1, w10=rw1*aw0, w11=rw1*aw1;
    int c00=ri0*12+ai0, c01=ri0*12+ai1, c10=ri1*12+ai0, c11=ri1*12+ai1;
    int t0 = __shfl_sync(0xffffffffu, c00, 0, 16);
    int t1 = __shfl_sync(0xffffffffu, c01, 0, 16);
    int t2 = __shfl_sync(0xffffffffu, c10, 0, 16);
    int t3 = __shfl_sync(0xffffffffu, c11, 0, 16);
    Mix mx;
    mx.c0 = (c00==t0?w00:0.f)+(c01==t0?w01:0.f)+(c10==t0?w10:0.f)+(c11==t0?w11:0.f);
    mx.c1 = (c00==t1?w00:0.f)+(c01==t1?w01:0.f)+(c10==t1?w10:0.f)+(c11==t1?w11:0.f);
    mx.c2 = (c00==t2?w00:0.f)+(c01==t2?w01:0.f)+(c10==t2?w10:0.f)+(c11==t2?w11:0.f);
    mx.c3 = (c00==t3?w00:0.f)+(c01==t3?w01:0.f)+(c10==t3?w10:0.f)+(c11==t3?w11:0.f);
    float den0 = gsum16(mx.c0), den1 = gsum16(mx.c1);
    float den2 = gsum16(mx.c2), den3 = gsum16(mx.c3);
    mx.m0 = w00/fmaxf(den0,EPSF); mx.m1 = w01/fmaxf(den1,EPSF);
    mx.m2 = w10/fmaxf(den2,EPSF); mx.m3 = w11/fmaxf(den3,EPSF);
    mx.s_k = mx.m0*den0 + mx.m1*den1 + mx.m2*den2 + mx.m3*den3;
    return mx;
}

// ---------------- small kernels ----------------
__global__ void zero_kernel(){
    int t = threadIdx.x;
    if (t < 34) g_mom[t] = 0.0;
    if (t < CC) { g_zs1[t]=0.0; g_zs2[t]=0.0; }
}

__global__ __launch_bounds__(256) void moments_kernel(const float* __restrict__ nxyz,
                                                      const float* __restrict__ cxyz){
    __shared__ double smom[34];
    int tid = threadIdx.x;
    if (tid < 34) smom[tid] = 0.0;
    __syncthreads();
    int p = blockIdx.x*256 + tid;
    Geo g = geom(nxyz, cxyz, p);
    float fc[4] = {g.dx, g.dy, g.dz, g.r};
    float fp[5] = {g.rn, g.sth, g.cth, g.sph, g.cph};
    float v[34];
#pragma unroll
    for (int i=0;i<4;i++){
        v[i] = fc[i];
#pragma unroll
        for (int j=i;j<4;j++) v[4 + i*4 - (i*(i-1))/2 + (j-i)] = fc[i]*fc[j];
    }
#pragma unroll
    for (int i=0;i<5;i++){
        v[14+i] = fp[i];
#pragma unroll
        for (int j=i;j<5;j++) v[19 + i*5 - (i*(i-1))/2 + (j-i)] = fp[i]*fp[j];
    }
#pragma unroll
    for (int i=0;i<34;i++){
        float s = wsum32(v[i]);
        if ((tid&31)==0) atomicAdd(&smom[i], (double)s);
    }
    __syncthreads();
    if (tid < 34) atomicAdd(&g_mom[tid], smom[tid]);
}

__global__ void setup_kernel(
    const float* __restrict__ cf_w1, const float* __restrict__ cf_b1,
    const float* __restrict__ cf_g,  const float* __restrict__ cf_be,
    const float* __restrict__ cf_w2, const float* __restrict__ cf_b2,
    const float* __restrict__ pf_w1, const float* __restrict__ pf_b1,
    const float* __restrict__ pf_g,  const float* __restrict__ pf_be,
    const float* __restrict__ pf_w2, const float* __restrict__ pf_b2,
    const float* __restrict__ ac_w,  const float* __restrict__ ac_b,
    const float* __restrict__ ap_w,  const float* __restrict__ ap_b,
    const float* __restrict__ gamma_p,
    const float* __restrict__ ge_w1, const float* __restrict__ ge_b1,
    const float* __restrict__ ge_w2)
{
    __shared__ float sT[CC*CC];
    __shared__ float sv1[CC], sv2[CC];
    int tid = threadIdx.x;
    float gam = gamma_p[0];
    const double inv = 1.0/(double)NPTS;

    if (tid < CC){
        { // cart BN fold
            double mu[4], cov[4][4];
#pragma unroll
            for (int i=0;i<4;i++) mu[i] = g_mom[i]*inv;
#pragma unroll
            for (int i=0;i<4;i++)
#pragma unroll
                for (int j=i;j<4;j++){
                    double c2 = g_mom[4 + i*4 - (i*(i-1))/2 + (j-i)]*inv - mu[i]*mu[j];
                    cov[i][j]=c2; cov[j][i]=c2;
                }
            double w[4], m=(double)cf_b1[tid], vv=0.0;
#pragma unroll
            for (int i=0;i<4;i++){ w[i]=(double)cf_w1[tid*4+i]; m += w[i]*mu[i]; }
#pragma unroll
            for (int i=0;i<4;i++)
#pragma unroll
                for (int j=0;j<4;j++) vv += w[i]*w[j]*cov[i][j];
            double al = (double)cf_g[tid]/sqrt(vv+1e-5);
#pragma unroll
            for (int i=0;i<4;i++) g_WcfT[i*CC+tid] = (float)(w[i]*al);
            g_bcf[tid] = (float)(((double)cf_b1[tid]-m)*al + (double)cf_be[tid]);
        }
        { // polar BN fold
            double mu[5], cov[5][5];
#pragma unroll
            for (int i=0;i<5;i++) mu[i] = g_mom[14+i]*inv;
#pragma unroll
            for (int i=0;i<5;i++)
#pragma unroll
                for (int j=i;j<5;j++){
                    double c2 = g_mom[19 + i*5 - (i*(i-1))/2 + (j-i)]*inv - mu[i]*mu[j];
                    cov[i][j]=c2; cov[j][i]=c2;
                }
            double w[5], m=(double)pf_b1[tid], vv=0.0;
#pragma unroll
            for (int i=0;i<5;i++){ w[i]=(double)pf_w1[tid*5+i]; m += w[i]*mu[i]; }
#pragma unroll
            for (int i=0;i<5;i++)
#pragma unroll
                for (int j=0;j<5;j++) vv += w[i]*w[j]*cov[i][j];
            double al = (double)pf_g[tid]/sqrt(vv+1e-5);
#pragma unroll
            for (int i=0;i<5;i++) g_WpfT[i*CC+tid] = (float)(w[i]*al);
            g_bpf[tid] = (float)(((double)pf_b1[tid]-m)*al + (double)pf_be[tid]);
        }
    }
    for (int e=tid;e<CC*CC;e+=blockDim.x){
        int m=e>>6, j=e&63; float s=0.f;
        for (int l=0;l<CC;l++) s += ac_w[m*CC+l]*cf_w2[l*CC+j];
        sT[e]=s;
    }
    __syncthreads();
    for (int e=tid;e<CC*CC;e+=blockDim.x){
        int c=e>>6, j=e&63; float s=0.f;
        for (int m=0;m<CC;m++) s += ge_w1[c*CC+m]*sT[m*CC+j];
        g_Wmain[j*CC+c]=s;
    }
    __syncthreads();
    for (int e=tid;e<CC*CC;e+=blockDim.x){
        int m=e>>6, j=e&63; float s=0.f;
        for (int l=0;l<CC;l++) s += ap_w[m*CC+l]*pf_w2[l*CC+j];
        sT[e]=s;
    }
    __syncthreads();
    for (int e=tid;e<CC*CC;e+=blockDim.x){
        int c=e>>6, j=e&63; float s=0.f;
        for (int m=0;m<CC;m++) s += ge_w1[c*CC+m]*sT[m*CC+j];
        g_Wmain[(64+j)*CC+c]=gam*s;
    }
    if (tid < CC){
        float s1 = ac_b[tid] + gam*ap_b[tid];
        for (int j=0;j<CC;j++) s1 += ac_w[tid*CC+j]*cf_b2[j];
        sv1[tid]=s1;
        float s2 = 0.f;
        for (int j=0;j<CC;j++) s2 += ap_w[tid*CC+j]*pf_b2[j];
        sv2[tid]=s2;
    }
    __syncthreads();
    if (tid < CC){
        float bz = ge_b1[tid], bp = 0.f;
        for (int m=0;m<CC;m++){ bz += ge_w1[tid*CC+m]*sv1[m]; bp += ge_w1[tid*CC+m]*sv2[m]; }
        g_bz[tid]=bz; g_bp[tid]=gam*bp;
    }
    __syncthreads();
    for (int e=tid; e<CC*128; e+=blockDim.x){
        int k = e & 127, c = e >> 7;
        float v = g_Wmain[k*CC + c];
        __nv_bfloat16 h = __float2bfloat16_rn(v);
        float rem = v - __bfloat162float(h);
        g_Whi[c*128 + k] = h;
        g_Wlo[c*128 + k] = __float2bfloat16_rn(rem);
    }
    for (int e=tid; e<CC*CC; e+=blockDim.x){
        int j = e & 63, c = e >> 6;
        float v = ge_w2[c*CC + j];
        __nv_bfloat16 h = __float2bfloat16_rn(v);
        float rem = v - __bfloat162float(h);
        g_W2hi[c*64 + j] = h;
        g_W2lo[c*64 + j] = __float2bfloat16_rn(rem);
    }
}

// ---------------- main kernel smem layout (bytes) ----------------
#define HSTR 136       // H rows: 272B stride (LDSM conflict-free, validated)
#define WSTR 136
#define GSTR 18        // group stride (floats) for padded HP/coef arrays: conflict-free float2
#define HPROW 144      // 8*18 floats per j-row
#define SH_HHI   0          // 34816
#define SH_HLO   34816      // -> 69632
#define SH_HP    69632      // 64*144*4 = 36864 -> 106496
#define SH_WHI   69632      // overlay (GEMM phase): 17408 -> 87040
#define SH_WLO   87040      // -> 104448
#define SH_CC    106496     // 4*144*4 = 2304 -> 108800  (coefs; reused as stats S1)
#define SH_MM    108800     // 2304 -> 111104             (coefs; reused as stats S2)
#define SH_SK    111104     // 512 -> 111616
#define SH_WCF   111616     // 1024 -> 112640
#define SH_WPF   112640     // 1280 -> 113920
#define SH_BCF   113920     // 256
#define SH_BPF   114176     // 256
#define SH_BZ    114432     // 256
#define SH_BP    114688     // 256
#define MAIN_SMEM 114944

__global__ __launch_bounds__(256,2) void main_kernel(const float* __restrict__ nxyz,
                                                     const float* __restrict__ cxyz){
    extern __shared__ char smc[];
    float* sHPf = (float*)(smc + SH_HP);
    float* sCc  = (float*)(smc + SH_CC);
    float* sMm  = (float*)(smc + SH_MM);
    float* sSK  = (float*)(smc + SH_SK);
    float* sWcf = (float*)(smc + SH_WCF);
    float* sWpf = (float*)(smc + SH_WPF);
    float* sbcf = (float*)(smc + SH_BCF);
    float* sbpf = (float*)(smc + SH_BPF);
    float* sbz  = (float*)(smc + SH_BZ);
    float* sbp  = (float*)(smc + SH_BP);
    int tid = threadIdx.x;
    int wid = tid >> 5;
    int lane = tid & 31;

    for (int i=tid;i<4*CC;i+=256) sWcf[i]=g_WcfT[i];
    for (int i=tid;i<5*CC;i+=256) sWpf[i]=g_WpfT[i];
    if (tid < CC){
        sbcf[tid]=g_bcf[tid]; sbpf[tid]=g_bpf[tid];
        sbz[tid]=g_bz[tid];   sbp[tid]=g_bp[tid];
    }
    __syncthreads();

    int p0 = blockIdx.x*128;
    int m  = tid & 127;
    int gp = (m>>4)*GSTR + (m&15);     // padded point offset within a j-row

    // phase A: geometry + mix coeffs (both halves compute their point's geometry)
    Geo g = geom(nxyz, cxyz, p0 + m);
    Mix mx = make_mix(g);
    if (tid < 128){
        sCc[0*HPROW/1*0 + 0] = sCc[0]; // no-op placeholder removed below
    }
    if (tid < 128){
        sCc[0*144 + gp] = mx.c0;  sCc[1*144 + gp] = mx.c1;
        sCc[2*144 + gp] = mx.c2;  sCc[3*144 + gp] = mx.c3;
        sMm[0*144 + gp] = mx.m0;  sMm[1*144 + gp] = mx.m1;
        sMm[2*144 + gp] = mx.m2;  sMm[3*144 + gp] = mx.m3;
        sSK[m] = mx.s_k;
    }

    // phase B: first layers, vectorized weight loads (j+=4)
    {
        int jh = (tid >> 7) * 32;
        char* Hhi = smc + SH_HHI;
        char* Hlo = smc + SH_HLO;
#pragma unroll 2
        for (int j0=jh; j0<jh+32; j0+=4){
            float4 wc0 = *(const float4*)(sWcf + j0);
            float4 wc1 = *(const float4*)(sWcf + 64 + j0);
            float4 wc2 = *(const float4*)(sWcf + 128 + j0);
            float4 wc3 = *(const float4*)(sWcf + 192 + j0);
            float4 bc  = *(const float4*)(sbcf + j0);
            float hc0 = fmaxf(bc.x + g.dx*wc0.x + g.dy*wc1.x + g.dz*wc2.x + g.r*wc3.x, 0.f);
            float hc1 = fmaxf(bc.y + g.dx*wc0.y + g.dy*wc1.y + g.dz*wc2.y + g.r*wc3.y, 0.f);
            float hc2 = fmaxf(bc.z + g.dx*wc0.z + g.dy*wc1.z + g.dz*wc2.z + g.r*wc3.z, 0.f);
            float hc3 = fmaxf(bc.w + g.dx*wc0.w + g.dy*wc1.w + g.dz*wc2.w + g.r*wc3.w, 0.f);
            uint32_t h01,l01,h23,l23;
            split2(hc0,hc1,h01,l01); split2(hc2,hc3,h23,l23);
            uint32_t off = (uint32_t)(m*HSTR + j0)*2;
            *(uint2*)(Hhi + off) = make_uint2(h01,h23);
            *(uint2*)(Hlo + off) = make_uint2(l01,l23);

            float4 wp0 = *(const float4*)(sWpf + j0);
            float4 wp1 = *(const float4*)(sWpf + 64 + j0);
            float4 wp2 = *(const float4*)(sWpf + 128 + j0);
            float4 wp3 = *(const float4*)(sWpf + 192 + j0);
            float4 wp4 = *(const float4*)(sWpf + 256 + j0);
            float4 bp4 = *(const float4*)(sbpf + j0);
            float q0 = fmaxf(bp4.x + g.rn*wp0.x + g.sth*wp1.x + g.cth*wp2.x + g.sph*wp3.x + g.cph*wp4.x, 0.f);
            float q1 = fmaxf(bp4.y + g.rn*wp0.y + g.sth*wp1.y + g.cth*wp2.y + g.sph*wp3.y + g.cph*wp4.y, 0.f);
            float q2 = fmaxf(bp4.z + g.rn*wp0.z + g.sth*wp1.z + g.cth*wp2.z + g.sph*wp3.z + g.cph*wp4.z, 0.f);
            float q3 = fmaxf(bp4.w + g.rn*wp0.w + g.sth*wp1.w + g.cth*wp2.w + g.sph*wp3.w + g.cph*wp4.w, 0.f);
            sHPf[(j0  )*HPROW + gp] = q0;
            sHPf[(j0+1)*HPROW + gp] = q1;
            sHPf[(j0+2)*HPROW + gp] = q2;
            sHPf[(j0+3)*HPROW + gp] = q3;
        }
    }
    __syncthreads();

    // mix: 512 tasks (64 j x 8 grp), float2 conflict-free (GSTR=18 padding)
#pragma unroll
    for (int t2i=0;t2i<2;t2i++){
        int tk = t2i*256 + tid;
        int j = tk>>3, grp = tk&7;
        float2* hrow = (float2*)(sHPf + j*HPROW + grp*GSTR);
        float2 h[8];
#pragma unroll
        for (int i=0;i<8;i++) h[i]=hrow[i];
        float gq[4];
#pragma unroll
        for (int q=0;q<4;q++){
            const float2* cv = (const float2*)(sCc + q*144 + grp*GSTR);
            float acc = 0.f;
#pragma unroll
            for (int i=0;i<8;i++){ float2 c=cv[i]; acc = fmaf(c.x,h[i].x,fmaf(c.y,h[i].y,acc)); }
            gq[q]=acc;
        }
        float2 o[8];
#pragma unroll
        for (int i=0;i<8;i++) o[i]=make_float2(0.f,0.f);
#pragma unroll
        for (int q=0;q<4;q++){
            const float2* mv = (const float2*)(sMm + q*144 + grp*GSTR);
            float gv = gq[q];
#pragma unroll
            for (int i=0;i<8;i++){ float2 mm=mv[i]; o[i].x = fmaf(mm.x,gv,o[i].x); o[i].y = fmaf(mm.y,gv,o[i].y); }
        }
#pragma unroll
        for (int i=0;i<8;i++) hrow[i]=o[i];
    }
    __syncthreads();

    // convert polar to bf16 H cols 64..127 (packed uint2 stores)
    {
        int ch = (tid >> 7) * 32;
        char* Hhi = smc + SH_HHI;
        char* Hlo = smc + SH_HLO;
#pragma unroll 2
        for (int jj=ch; jj<ch+32; jj+=4){
            float v0 = sHPf[(jj  )*HPROW + gp];
            float v1 = sHPf[(jj+1)*HPROW + gp];
            float v2 = sHPf[(jj+2)*HPROW + gp];
            float v3 = sHPf[(jj+3)*HPROW + gp];
            uint32_t h01,l01,h23,l23;
            split2(v0,v1,h01,l01); split2(v2,v3,h23,l23);
            uint32_t off = (uint32_t)(m*HSTR + 64 + jj)*2;
            *(uint2*)(Hhi + off) = make_uint2(h01,h23);
            *(uint2*)(Hlo + off) = make_uint2(l01,l23);
        }
    }
    __syncthreads();   // HP scratch dead -> W tiles overlay

    // copy W tiles into overlaid smem; zero stats staging
    {
        int c = tid >> 2, q = tid & 3;
        const uint4* gh = (const uint4*)(g_Whi + c*128 + q*32);
        const uint4* gl = (const uint4*)(g_Wlo + c*128 + q*32);
        uint4* shh = (uint4*)(smc + SH_WHI + (c*WSTR + q*32)*2);
        uint4* shl = (uint4*)(smc + SH_WLO + (c*WSTR + q*32)*2);
#pragma unroll
        for (int i=0;i<4;i++){ shh[i]=gh[i]; shl[i]=gl[i]; }
    }
    if (tid < CC){ sCc[tid]=0.f; sMm[tid]=0.f; }
    __syncthreads();

    // GEMM via mma.sync bf16, ldmatrix fragment feeds (validated R9/R10)
    {
        int gq2 = lane >> 2;
        int t2 = (lane & 3) * 2;
        int c0 = (wid & 3) * 16;
        int ph = (wid >> 2) * 64;
        int r0 = c0 + gq2, r1 = c0 + gq2 + 8;
        int lrow = lane & 7, lgrp = lane >> 3;

        uint32_t Ah[8][4], Al[8][4];
        {
            uint32_t arow = (uint32_t)(c0 + (lgrp & 1)*8 + lrow);
            uint32_t acol = (uint32_t)((lgrp >> 1) * 8);
            uint32_t bh = smem_u32(smc + SH_WHI) + (arow*WSTR + acol)*2;
            uint32_t bl = smem_u32(smc + SH_WLO) + (arow*WSTR + acol)*2;
#pragma unroll
            for (int ks=0; ks<8; ks++){
                LDSM_X4(Ah[ks][0],Ah[ks][1],Ah[ks][2],Ah[ks][3], bh + ks*32);
                LDSM_X4(Al[ks][0],Al[ks][1],Al[ks][2],Al[ks][3], bl + ks*32);
            }
        }
        uint32_t hbase = smem_u32(smc + SH_HHI);
        uint32_t lbase = smem_u32(smc + SH_HLO);
        float bz0 = sbz[r0], bz1 = sbz[r1], bp0 = sbp[r0], bp1 = sbp[r1];
        float s10=0.f, s20=0.f, s11=0.f, s21=0.f;
#pragma unroll 1
        for (int nt=0; nt<8; nt++){
            int pn = ph + nt*8;
            uint32_t badh = hbase + (uint32_t)((pn + lrow)*HSTR + lgrp*8)*2;
            uint32_t badl = lbase + (uint32_t)((pn + lrow)*HSTR + lgrp*8)*2;
            uint32_t Bh[16], Bl[16];
#pragma unroll
            for (int kq=0; kq<4; kq++){
                LDSM_X4(Bh[kq*4+0],Bh[kq*4+1],Bh[kq*4+2],Bh[kq*4+3], badh + kq*64);
                LDSM_X4(Bl[kq*4+0],Bl[kq*4+1],Bl[kq*4+2],Bl[kq*4+3], badl + kq*64);
            }
            float a0=0.f, a1=0.f, a2=0.f, a3=0.f;
#pragma unroll
            for (int ks=0; ks<8; ks++){
                uint32_t bh0 = Bh[2*ks], bh1 = Bh[2*ks+1];
                uint32_t bl0 = Bl[2*ks], bl1 = Bl[2*ks+1];
                MMA_BF16(a0,a1,a2,a3, Ah[ks][0],Ah[ks][1],Ah[ks][2],Ah[ks][3], bh0,bh1);
                MMA_BF16(a0,a1,a2,a3, Ah[ks][0],Ah[ks][1],Ah[ks][2],Ah[ks][3], bl0,bl1);
                MMA_BF16(a0,a1,a2,a3, Al[ks][0],Al[ks][1],Al[ks][2],Al[ks][3], bh0,bh1);
            }
            int col = pn + t2;
            float sk0 = sSK[col], sk1 = sSK[col+1];
            float z00 = a0 + fmaf(bp0, sk0, bz0);
            float z01 = a1 + fmaf(bp0, sk1, bz0);
            float z10 = a2 + fmaf(bp1, sk0, bz1);
            float z11 = a3 + fmaf(bp1, sk1, bz1);
            *(float2*)(g_z1 + (size_t)r0*NPTS + p0 + col) = make_float2(z00,z01);
            *(float2*)(g_z1 + (size_t)r1*NPTS + p0 + col) = make_float2(z10,z11);
            s10 += z00+z01; s20 += z00*z00+z01*z01;
            s11 += z10+z11; s21 += z10*z10+z11*z11;
        }
        s10 += __shfl_xor_sync(0xffffffffu, s10, 1); s10 += __shfl_xor_sync(0xffffffffu, s10, 2);
        s20 += __shfl_xor_sync(0xffffffffu, s20, 1); s20 += __shfl_xor_sync(0xffffffffu, s20, 2);
        s11 += __shfl_xor_sync(0xffffffffu, s11, 1); s11 += __shfl_xor_sync(0xffffffffu, s11, 2);
        s21 += __shfl_xor_sync(0xffffffffu, s21, 1); s21 += __shfl_xor_sync(0xffffffffu, s21, 2);
        if ((lane & 3) == 0){
            atomicAdd(&sCc[r0], s10); atomicAdd(&sMm[r0], s20);
            atomicAdd(&sCc[r1], s11); atomicAdd(&sMm[r1], s21);
        }
    }
    __syncthreads();
    if (tid < CC){
        atomicAdd(&g_zs1[tid], (double)sCc[tid]);
        atomicAdd(&g_zs2[tid], (double)sMm[tid]);
    }
}

__global__ void bnstats_kernel(const float* __restrict__ ge_g, const float* __restrict__ ge_be){
    int c = threadIdx.x;
    if (c < CC){
        double mean = g_zs1[c]/(double)NPTS;
        double var  = g_zs2[c]/(double)NPTS - mean*mean;
        double a = (double)ge_g[c]/sqrt(var + 1e-5);
        g_alpha[c] = (float)a;
        g_beta[c]  = (float)((double)ge_be[c] - mean*a);
    }
}

// ---------------- final kernel (unchanged from R10) ----------------
#define FSTR 72
#define F2STR 72
#define FH_HHI 0
#define FH_HLO 18432
#define FH_WHI 36864
#define FH_WLO 46080
#define FH_A   55296
#define FH_BV  55552
#define FH_B2  55808
#define FINAL_SMEM 56064

__global__ __launch_bounds__(256,2) void final_kernel(const float* __restrict__ ge_b2,
                                                      float* __restrict__ out){
    extern __shared__ char smc[];
    float* sa  = (float*)(smc + FH_A);
    float* sbv = (float*)(smc + FH_BV);
    float* sb2 = (float*)(smc + FH_B2);
    int tid = threadIdx.x;
    int wid = tid >> 5;
    int lane = tid & 31;

    {
        int c = tid >> 2, q = tid & 3;
        const uint4* gh = (const uint4*)(g_W2hi + c*64 + q*16);
        const uint4* gl = (const uint4*)(g_W2lo + c*64 + q*16);
        uint4* shh = (uint4*)(smc + FH_WHI + (c*F2STR + q*16)*2);
        uint4* shl = (uint4*)(smc + FH_WLO + (c*F2STR + q*16)*2);
#pragma unroll
        for (int i=0;i<2;i++){ shh[i]=gh[i]; shl[i]=gl[i]; }
    }
    if (tid < CC){ sa[tid]=g_alpha[tid]; sbv[tid]=g_beta[tid]; sb2[tid]=ge_b2[tid]; }
    __syncthreads();

    int p0 = blockIdx.x*128;

    {
        int m = tid & 127;
        int ch = (tid >> 7) * 32;
        char* Hhi = smc + FH_HHI;
        char* Hlo = smc + FH_HLO;
#pragma unroll 2
        for (int c=ch; c<ch+32; c+=4){
            float z0 = g_z1[(size_t)c*NPTS + p0 + m];
            float z1v = g_z1[(size_t)(c+1)*NPTS + p0 + m];
            float z2 = g_z1[(size_t)(c+2)*NPTS + p0 + m];
            float z3 = g_z1[(size_t)(c+3)*NPTS + p0 + m];
            float h0 = fmaxf(fmaf(z0, sa[c], sbv[c]), 0.f);
            float h1 = fmaxf(fmaf(z1v, sa[c+1], sbv[c+1]), 0.f);
            float h2 = fmaxf(fmaf(z2, sa[c+2], sbv[c+2]), 0.f);
            float h3 = fmaxf(fmaf(z3, sa[c+3], sbv[c+3]), 0.f);
            uint32_t h01,l01,h23,l23;
            split2(h0,h1,h01,l01); split2(h2,h3,h23,l23);
            uint32_t off = (uint32_t)(m*FSTR + c)*2;
            *(uint2*)(Hhi + off) = make_uint2(h01,h23);
            *(uint2*)(Hlo + off) = make_uint2(l01,l23);
        }
    }
    __syncthreads();

    {
        int g = lane >> 2;
        int t2 = (lane & 3) * 2;
        int c0 = (wid & 3) * 16;
        int ph = (wid >> 2) * 64;
        int r0 = c0 + g, r1 = c0 + g + 8;
        int lrow = lane & 7, lgrp = lane >> 3;

        uint32_t Ah[4][4], Al[4][4];
        {
            uint32_t arow = (uint32_t)(c0 + (lgrp & 1)*8 + lrow);
            uint32_t acol = (uint32_t)((lgrp >> 1) * 8);
            uint32_t bh = smem_u32(smc + FH_WHI) + (arow*F2STR + acol)*2;
            uint32_t bl = smem_u32(smc + FH_WLO) + (arow*F2STR + acol)*2;
#pragma unroll
            for (int ks=0; ks<4; ks++){
                LDSM_X4(Ah[ks][0],Ah[ks][1],Ah[ks][2],Ah[ks][3], bh + ks*32);
                LDSM_X4(Al[ks][0],Al[ks][1],Al[ks][2],Al[ks][3], bl + ks*32);
            }
        }
        uint32_t hbase = smem_u32(smc + FH_HHI);
        uint32_t lbase = smem_u32(smc + FH_HLO);
        float b0v = sb2[r0], b1v = sb2[r1];
        int b = p0 >> 16;
        int nk0 = p0 & 65535;
        float* ob = out + (size_t)b*CC*65536;
#pragma unroll 1
        for (int nt=0; nt<8; nt++){
            int pn = ph + nt*8;
            uint32_t badh = hbase + (uint32_t)((pn + lrow)*FSTR + lgrp*8)*2;
            uint32_t badl = lbase + (uint32_t)((pn + lrow)*FSTR + lgrp*8)*2;
            uint32_t Bh[8], Bl[8];
#pragma unroll
            for (int kq=0; kq<2; kq++){
                LDSM_X4(Bh[kq*4+0],Bh[kq*4+1],Bh[kq*4+2],Bh[kq*4+3], badh + kq*64);
                LDSM_X4(Bl[kq*4+0],Bl[kq*4+1],Bl[kq*4+2],Bl[kq*4+3], badl + kq*64);
            }
            float a0=0.f, a1=0.f, a2=0.f, a3=0.f;
#pragma unroll
            for (int ks=0; ks<4; ks++){
                uint32_t bh0 = Bh[2*ks], bh1 = Bh[2*ks+1];
                uint32_t bl0 = Bl[2*ks], bl1 = Bl[2*ks+1];
                MMA_BF16(a0,a1,a2,a3, Ah[ks][0],Ah[ks][1],Ah[ks][2],Ah[ks][3], bh0,bh1);
                MMA_BF16(a0,a1,a2,a3, Ah[ks][0],Ah[ks][1],Ah[ks][2],Ah[ks][3], bl0,bl1);
                MMA_BF16(a0,a1,a2,a3, Al[ks][0],Al[ks][1],Al[ks][2],Al[ks][3], bh0,bh1);
            }
            int col = pn + t2;
            *(float2*)(ob + (size_t)r0*65536 + nk0 + col) = make_float2(a0+b0v, a1+b0v);
            *(float2*)(ob + (size_t)r1*65536 + nk0 + col) = make_float2(a2+b1v, a3+b1v);
        }
    }
}

extern "C" void kernel_launch(void* const* d_in, const int* in_sizes, int n_in,
                              void* d_out, int out_size){
    const float* nxyz  = (const float*)d_in[0];
    const float* cxyz  = (const float*)d_in[1];
    const float* cf_w1 = (const float*)d_in[2];
    const float* cf_b1 = (const float*)d_in[3];
    const float* cf_g  = (const float*)d_in[4];
    const float* cf_be = (const float*)d_in[5];
    const float* cf_w2 = (const float*)d_in[6];
    const float* cf_b2 = (const float*)d_in[7];
    const float* pf_w1 = (const float*)d_in[8];
    const float* pf_b1 = (const float*)d_in[9];
    const float* pf_g  = (const float*)d_in[10];
    const float* pf_be = (const float*)d_in[11];
    const float* pf_w2 = (const float*)d_in[12];
    const float* pf_b2 = (const float*)d_in[13];
    const float* ac_w  = (const float*)d_in[14];
    const float* ac_b  = (const float*)d_in[15];
    const float* ap_w  = (const float*)d_in[16];
    const float* ap_b  = (const float*)d_in[17];
    const float* gamma = (const float*)d_in[18];
    const float* ge_w1 = (const float*)d_in[19];
    const float* ge_b1 = (const float*)d_in[20];
    const float* ge_g  = (const float*)d_in[21];
    const float* ge_be = (const float*)d_in[22];
    const float* ge_w2 = (const float*)d_in[23];
    const float* ge_b2 = (const float*)d_in[24];
    float* out = (float*)d_out;

    cudaFuncSetAttribute(main_kernel, cudaFuncAttributeMaxDynamicSharedMemorySize, MAIN_SMEM);
    cudaFuncSetAttribute(final_kernel, cudaFuncAttributeMaxDynamicSharedMemorySize, FINAL_SMEM);

    zero_kernel<<<1, 64>>>();
    moments_kernel<<<NPTS/256, 256>>>(nxyz, cxyz);
    setup_kernel<<<1, 256>>>(cf_w1, cf_b1, cf_g, cf_be, cf_w2, cf_b2,
                             pf_w1, pf_b1, pf_g, pf_be, pf_w2, pf_b2,
                             ac_w, ac_b, ap_w, ap_b, gamma,
                             ge_w1, ge_b1, ge_w2);
    main_kernel<<<NPTS/128, 256, MAIN_SMEM>>>(nxyz, cxyz);
    bnstats_kernel<<<1, 64>>>(ge_g, ge_be);
    final_kernel<<<NPTS/128, 256, FINAL_SMEM>>>(ge_b2, out);
}

// round 13
// speedup vs baseline: 1.5766x; 1.1363x over previous
#include <cuda_runtime.h>
#include <cuda_bf16.h>
#include <math.h>
#include <stdint.h>

#define BB 8
#define NN 4096
#define KK 16
#define CC 64
#define NPTS (BB*NN*KK)
#define EPSF 1e-6f
#define PI_F 3.14159265358979323846f

// ---------------- device globals ----------------
__device__ double g_mom[34];
__device__ double g_zs1[CC];
__device__ double g_zs2[CC];
__device__ float  g_WcfT[4*CC];
__device__ float  g_bcf[CC];
__device__ float  g_WpfT[5*CC];
__device__ float  g_bpf[CC];
__device__ float  g_Wmain[128*CC];   // [k][c]
__device__ float  g_bz[CC];
__device__ float  g_bp[CC];
__device__ float  g_alpha[CC];
__device__ float  g_beta[CC];
__device__ float  g_z1[CC*NPTS];     // [c][p]
// bf16 split weights [c][k] row-major (k 0..63 cart, 64..127 polar)
__device__ __nv_bfloat16 g_Whi[CC*128];
__device__ __nv_bfloat16 g_Wlo[CC*128];
__device__ __nv_bfloat16 g_W2hi[CC*CC];
__device__ __nv_bfloat16 g_W2lo[CC*CC];

// ---------------- helpers ----------------
#define MMA_BF16(d0,d1,d2,d3,a0,a1,a2,a3,b0,b1) \
    asm volatile("mma.sync.aligned.m16n8k16.row.col.f32.bf16.bf16.f32 " \
        "{%0,%1,%2,%3}, {%4,%5,%6,%7}, {%8,%9}, {%0,%1,%2,%3};" \
        : "+f"(d0),"+f"(d1),"+f"(d2),"+f"(d3) \
        : "r"(a0),"r"(a1),"r"(a2),"r"(a3),"r"(b0),"r"(b1))

#define LDSM_X4(r0,r1,r2,r3, addr) \
    asm volatile("ldmatrix.sync.aligned.m8n8.x4.shared.b16 {%0,%1,%2,%3}, [%4];" \
        : "=r"(r0),"=r"(r1),"=r"(r2),"=r"(r3) : "r"(addr))

__device__ __forceinline__ uint32_t smem_u32(const void* p){
    uint32_t a;
    asm("{ .reg .u64 t; cvta.to.shared.u64 t, %1; cvt.u32.u64 %0, t; }" : "=r"(a) : "l"(p));
    return a;
}

__device__ __forceinline__ uint32_t pack_bf(float v0, float v1){
    __nv_bfloat16 h0 = __float2bfloat16_rn(v0);
    __nv_bfloat16 h1 = __float2bfloat16_rn(v1);
    return (uint32_t)(*(uint16_t*)&h0) | ((uint32_t)(*(uint16_t*)&h1) << 16);
}
__device__ __forceinline__ void split2(float v0, float v1, uint32_t& hp, uint32_t& lp){
    __nv_bfloat16 h0 = __float2bfloat16_rn(v0);
    __nv_bfloat16 h1 = __float2bfloat16_rn(v1);
    float r0 = v0 - __bfloat162float(h0);
    float r1 = v1 - __bfloat162float(h1);
    hp = (uint32_t)(*(uint16_t*)&h0) | ((uint32_t)(*(uint16_t*)&h1) << 16);
    lp = pack_bf(r0, r1);
}

__device__ __forceinline__ float wsum32(float v){
#pragma unroll
    for (int m=1; m<32; m<<=1) v += __shfl_xor_sync(0xffffffffu, v, m);
    return v;
}
__device__ __forceinline__ float gsum16(float v){
#pragma unroll
    for (int m=1; m<16; m<<=1) v += __shfl_xor_sync(0xffffffffu, v, m);
    return v;
}
__device__ __forceinline__ int clampi(int x,int lo,int hi){return x<lo?lo:(x>hi?hi:x);}

struct Geo { float dx,dy,dz,r,rn,sth,cth,sph,cph,theta; };
__device__ __forceinline__ Geo geom(const float* __restrict__ nxyz,
                                    const float* __restrict__ cxyz, int p){
    int b = p>>16, n = (p>>4)&(NN-1), k = p&(KK-1);
    int cb = (b*3)*NN + n;
    float cx=cxyz[cb], cy=cxyz[cb+NN], cz=cxyz[cb+2*NN];
    int nb = ((b*3)*NN + n)*KK + k;
    Geo g;
    g.dx = nxyz[nb]         - cx;
    g.dy = nxyz[nb+NN*KK]   - cy;
    g.dz = nxyz[nb+2*NN*KK] - cz;
    float r = sqrtf(g.dx*g.dx + g.dy*g.dy + g.dz*g.dz); r = fmaxf(r, EPSF);
    float rho = fmaxf(sqrtf(g.dx*g.dx + g.dy*g.dy), EPSF);
    g.r = r;
    g.theta = atan2f(g.dy, g.dx);
    float phi = atan2f(g.dz, rho);
    float rmean = gsum16(r) * (1.0f/16.0f);
    g.rn = fminf(r/(rmean+EPSF), 3.0f) * (1.0f/3.0f);
    sincosf(g.theta, &g.sth, &g.cth);
    sincosf(phi, &g.sph, &g.cph);
    return g;
}
struct Mix { float c0,c1,c2,c3, m0,m1,m2,m3, s_k; };
__device__ __forceinline__ Mix make_mix(const Geo& g){
    float ridx = g.rn*(2.0f - 1e-6f);
    float aidx = ((g.theta + PI_F)*(0.5f/PI_F))*(12.0f - 1e-6f);
    float ri0f = floorf(ridx); float rw1 = ridx-ri0f, rw0 = 1.0f-rw1;
    int ri0 = clampi((int)ri0f,0,1), ri1 = clampi((int)ri0f+1,0,1);
    float ai0f = floorf(aidx); float aw1 = aidx-ai0f, aw0 = 1.0f-aw1;
    int ai0 = clampi((int)ai0f,0,11), ai1 = clampi((int)ai0f+1,0,11);
    float w00=rw0*aw0, w01=rw0*aw1, w10=rw1*aw0, w11=rw1*aw1;
    int c00=ri0*12+ai0, c01=ri0*12+ai1, c10=ri1*12+ai0, c11=ri1*12+ai1;
    int t0 = __shfl_sync(0xffffffffu, c00, 0, 16);
    int t1 = __shfl_sync(0xffffffffu, c01, 0, 16);
    int t2 = __shfl_sync(0xffffffffu, c10, 0, 16);
    int t3 = __shfl_sync(0xffffffffu, c11, 0, 16);
    Mix mx;
    mx.c0 = (c00==t0?w00:0.f)+(c01==t0?w01:0.f)+(c10==t0?w10:0.f)+(c11==t0?w11:0.f);
    mx.c1 = (c00==t1?w00:0.f)+(c01==t1?w01:0.f)+(c10==t1?w10:0.f)+(c11==t1?w11:0.f);
    mx.c2 = (c00==t2?w00:0.f)+(c01==t2?w01:0.f)+(c10==t2?w10:0.f)+(c11==t2?w11:0.f);
    mx.c3 = (c00==t3?w00:0.f)+(c01==t3?w01:0.f)+(c10==t3?w10:0.f)+(c11==t3?w11:0.f);
    float den0 = gsum16(mx.c0), den1 = gsum16(mx.c1);
    float den2 = gsum16(mx.c2), den3 = gsum16(mx.c3);
    mx.m0 = w00/fmaxf(den0,EPSF); mx.m1 = w01/fmaxf(den1,EPSF);
    mx.m2 = w10/fmaxf(den2,EPSF); mx.m3 = w11/fmaxf(den3,EPSF);
    mx.s_k = mx.m0*den0 + mx.m1*den1 + mx.m2*den2 + mx.m3*den3;
    return mx;
}

// ---------------- small kernels ----------------
__global__ void zero_kernel(){
    int t = threadIdx.x;
    if (t < 34) g_mom[t] = 0.0;
    if (t < CC) { g_zs1[t]=0.0; g_zs2[t]=0.0; }
}

__global__ __launch_bounds__(256) void moments_kernel(const float* __restrict__ nxyz,
                                                      const float* __restrict__ cxyz){
    __shared__ double smom[34];
    int tid = threadIdx.x;
    if (tid < 34) smom[tid] = 0.0;
    __syncthreads();
    int p = blockIdx.x*256 + tid;
    Geo g = geom(nxyz, cxyz, p);
    float fc[4] = {g.dx, g.dy, g.dz, g.r};
    float fp[5] = {g.rn, g.sth, g.cth, g.sph, g.cph};
    float v[34];
#pragma unroll
    for (int i=0;i<4;i++){
        v[i] = fc[i];
#pragma unroll
        for (int j=i;j<4;j++) v[4 + i*4 - (i*(i-1))/2 + (j-i)] = fc[i]*fc[j];
    }
#pragma unroll
    for (int i=0;i<5;i++){
        v[14+i] = fp[i];
#pragma unroll
        for (int j=i;j<5;j++) v[19 + i*5 - (i*(i-1))/2 + (j-i)] = fp[i]*fp[j];
    }
#pragma unroll
    for (int i=0;i<34;i++){
        float s = wsum32(v[i]);
        if ((tid&31)==0) atomicAdd(&smom[i], (double)s);
    }
    __syncthreads();
    if (tid < 34) atomicAdd(&g_mom[tid], smom[tid]);
}

__global__ void setup_kernel(
    const float* __restrict__ cf_w1, const float* __restrict__ cf_b1,
    const float* __restrict__ cf_g,  const float* __restrict__ cf_be,
    const float* __restrict__ cf_w2, const float* __restrict__ cf_b2,
    const float* __restrict__ pf_w1, const float* __restrict__ pf_b1,
    const float* __restrict__ pf_g,  const float* __restrict__ pf_be,
    const float* __restrict__ pf_w2, const float* __restrict__ pf_b2,
    const float* __restrict__ ac_w,  const float* __restrict__ ac_b,
    const float* __restrict__ ap_w,  const float* __restrict__ ap_b,
    const float* __restrict__ gamma_p,
    const float* __restrict__ ge_w1, const float* __restrict__ ge_b1,
    const float* __restrict__ ge_w2)
{
    __shared__ float sT[CC*CC];
    __shared__ float sv1[CC], sv2[CC];
    int tid = threadIdx.x;
    float gam = gamma_p[0];
    const double inv = 1.0/(double)NPTS;

    if (tid < CC){
        { // cart BN fold
            double mu[4], cov[4][4];
#pragma unroll
            for (int i=0;i<4;i++) mu[i] = g_mom[i]*inv;
#pragma unroll
            for (int i=0;i<4;i++)
#pragma unroll
                for (int j=i;j<4;j++){
                    double c2 = g_mom[4 + i*4 - (i*(i-1))/2 + (j-i)]*inv - mu[i]*mu[j];
                    cov[i][j]=c2; cov[j][i]=c2;
                }
            double w[4], m=(double)cf_b1[tid], vv=0.0;
#pragma unroll
            for (int i=0;i<4;i++){ w[i]=(double)cf_w1[tid*4+i]; m += w[i]*mu[i]; }
#pragma unroll
            for (int i=0;i<4;i++)
#pragma unroll
                for (int j=0;j<4;j++) vv += w[i]*w[j]*cov[i][j];
            double al = (double)cf_g[tid]/sqrt(vv+1e-5);
#pragma unroll
            for (int i=0;i<4;i++) g_WcfT[i*CC+tid] = (float)(w[i]*al);
            g_bcf[tid] = (float)(((double)cf_b1[tid]-m)*al + (double)cf_be[tid]);
        }
        { // polar BN fold
            double mu[5], cov[5][5];
#pragma unroll
            for (int i=0;i<5;i++) mu[i] = g_mom[14+i]*inv;
#pragma unroll
            for (int i=0;i<5;i++)
#pragma unroll
                for (int j=i;j<5;j++){
                    double c2 = g_mom[19 + i*5 - (i*(i-1))/2 + (j-i)]*inv - mu[i]*mu[j];
                    cov[i][j]=c2; cov[j][i]=c2;
                }
            double w[5], m=(double)pf_b1[tid], vv=0.0;
#pragma unroll
            for (int i=0;i<5;i++){ w[i]=(double)pf_w1[tid*5+i]; m += w[i]*mu[i]; }
#pragma unroll
            for (int i=0;i<5;i++)
#pragma unroll
                for (int j=0;j<5;j++) vv += w[i]*w[j]*cov[i][j];
            double al = (double)pf_g[tid]/sqrt(vv+1e-5);
#pragma unroll
            for (int i=0;i<5;i++) g_WpfT[i*CC+tid] = (float)(w[i]*al);
            g_bpf[tid] = (float)(((double)pf_b1[tid]-m)*al + (double)pf_be[tid]);
        }
    }
    for (int e=tid;e<CC*CC;e+=blockDim.x){
        int m=e>>6, j=e&63; float s=0.f;
        for (int l=0;l<CC;l++) s += ac_w[m*CC+l]*cf_w2[l*CC+j];
        sT[e]=s;
    }
    __syncthreads();
    for (int e=tid;e<CC*CC;e+=blockDim.x){
        int c=e>>6, j=e&63; float s=0.f;
        for (int m=0;m<CC;m++) s += ge_w1[c*CC+m]*sT[m*CC+j];
        g_Wmain[j*CC+c]=s;
    }
    __syncthreads();
    for (int e=tid;e<CC*CC;e+=blockDim.x){
        int m=e>>6, j=e&63; float s=0.f;
        for (int l=0;l<CC;l++) s += ap_w[m*CC+l]*pf_w2[l*CC+j];
        sT[e]=s;
    }
    __syncthreads();
    for (int e=tid;e<CC*CC;e+=blockDim.x){
        int c=e>>6, j=e&63; float s=0.f;
        for (int m=0;m<CC;m++) s += ge_w1[c*CC+m]*sT[m*CC+j];
        g_Wmain[(64+j)*CC+c]=gam*s;
    }
    if (tid < CC){
        float s1 = ac_b[tid] + gam*ap_b[tid];
        for (int j=0;j<CC;j++) s1 += ac_w[tid*CC+j]*cf_b2[j];
        sv1[tid]=s1;
        float s2 = 0.f;
        for (int j=0;j<CC;j++) s2 += ap_w[tid*CC+j]*pf_b2[j];
        sv2[tid]=s2;
    }
    __syncthreads();
    if (tid < CC){
        float bz = ge_b1[tid], bp = 0.f;
        for (int m=0;m<CC;m++){ bz += ge_w1[tid*CC+m]*sv1[m]; bp += ge_w1[tid*CC+m]*sv2[m]; }
        g_bz[tid]=bz; g_bp[tid]=gam*bp;
    }
    __syncthreads();
    for (int e=tid; e<CC*128; e+=blockDim.x){
        int k = e & 127, c = e >> 7;
        float v = g_Wmain[k*CC + c];
        __nv_bfloat16 h = __float2bfloat16_rn(v);
        float rem = v - __bfloat162float(h);
        g_Whi[c*128 + k] = h;
        g_Wlo[c*128 + k] = __float2bfloat16_rn(rem);
    }
    for (int e=tid; e<CC*CC; e+=blockDim.x){
        int j = e & 63, c = e >> 6;
        float v = ge_w2[c*CC + j];
        __nv_bfloat16 h = __float2bfloat16_rn(v);
        float rem = v - __bfloat162float(h);
        g_W2hi[c*64 + j] = h;
        g_W2lo[c*64 + j] = __float2bfloat16_rn(rem);
    }
}

// ---------------- main kernel smem layout (bytes) ----------------
#define HSTR 72        // cart H rows: 144B stride (LDSM conflict-free, validated in final)
#define WSTR 72
#define USTR 72
#define GSTR 18
#define HPROW 144
#define SH_HHI   0          // 128*144 = 18432
#define SH_HLO   18432      // -> 36864
#define SH_HP    36864      // 64*144*4 = 36864 -> 73728 (overlaid by W tiles after u-phase)
#define SH_WCHI  36864      // 64*144 = 9216 -> 46080
#define SH_WCLO  46080      // -> 55296
#define SH_WPHI  55296      // -> 64512
#define SH_WPLO  64512      // -> 73728
#define SH_UHI   73728      // 32*144 = 4608 -> 78336
#define SH_ULO   78336      // -> 82944
#define SH_V     82944      // 64*36*4 = 9216 -> 92160
#define SH_CC    92160      // 4*144*4 = 2304 -> 94464 (coefs; reused as stats)
#define SH_MK    94464      // 128*4*4 = 2048 -> 96512
#define SH_SK    96512      // 512 -> 97024
#define SH_WCF   97024      // 1024 -> 98048
#define SH_WPF   98048      // 1280 -> 99328
#define SH_BCF   99328
#define SH_BPF   99584
#define SH_BZ    99840
#define SH_BP    100096
#define MAIN_SMEM 100352

__global__ __launch_bounds__(256,2) void main_kernel(const float* __restrict__ nxyz,
                                                     const float* __restrict__ cxyz){
    extern __shared__ char smc[];
    float* sHPf = (float*)(smc + SH_HP);
    float* sV   = (float*)(smc + SH_V);
    float* sCc  = (float*)(smc + SH_CC);
    float* sMK  = (float*)(smc + SH_MK);
    float* sSK  = (float*)(smc + SH_SK);
    float* sWcf = (float*)(smc + SH_WCF);
    float* sWpf = (float*)(smc + SH_WPF);
    float* sbcf = (float*)(smc + SH_BCF);
    float* sbpf = (float*)(smc + SH_BPF);
    float* sbz  = (float*)(smc + SH_BZ);
    float* sbp  = (float*)(smc + SH_BP);
    int tid = threadIdx.x;
    int wid = tid >> 5;
    int lane = tid & 31;

    for (int i=tid;i<4*CC;i+=256) sWcf[i]=g_WcfT[i];
    for (int i=tid;i<5*CC;i+=256) sWpf[i]=g_WpfT[i];
    if (tid < CC){
        sbcf[tid]=g_bcf[tid]; sbpf[tid]=g_bpf[tid];
        sbz[tid]=g_bz[tid];   sbp[tid]=g_bp[tid];
    }
    __syncthreads();

    int p0 = blockIdx.x*128;
    int m  = tid & 127;
    int gp = (m>>4)*GSTR + (m&15);

    // phase A: geometry + mix coefs
    Geo g = geom(nxyz, cxyz, p0 + m);
    Mix mx = make_mix(g);
    if (tid < 128){
        sCc[0*144 + gp] = mx.c0;  sCc[1*144 + gp] = mx.c1;
        sCc[2*144 + gp] = mx.c2;  sCc[3*144 + gp] = mx.c3;
        *(float4*)(sMK + m*4) = make_float4(mx.m0, mx.m1, mx.m2, mx.m3);
        sSK[m] = mx.s_k;
    }

    // phase B: first layers (cart -> H split tile; polar -> fp32 padded staging)
    {
        int jh = (tid >> 7) * 32;
        char* Hhi = smc + SH_HHI;
        char* Hlo = smc + SH_HLO;
#pragma unroll 2
        for (int j0=jh; j0<jh+32; j0+=4){
            float4 wc0 = *(const float4*)(sWcf + j0);
            float4 wc1 = *(const float4*)(sWcf + 64 + j0);
            float4 wc2 = *(const float4*)(sWcf + 128 + j0);
            float4 wc3 = *(const float4*)(sWcf + 192 + j0);
            float4 bc  = *(const float4*)(sbcf + j0);
            float hc0 = fmaxf(bc.x + g.dx*wc0.x + g.dy*wc1.x + g.dz*wc2.x + g.r*wc3.x, 0.f);
            float hc1 = fmaxf(bc.y + g.dx*wc0.y + g.dy*wc1.y + g.dz*wc2.y + g.r*wc3.y, 0.f);
            float hc2 = fmaxf(bc.z + g.dx*wc0.z + g.dy*wc1.z + g.dz*wc2.z + g.r*wc3.z, 0.f);
            float hc3 = fmaxf(bc.w + g.dx*wc0.w + g.dy*wc1.w + g.dz*wc2.w + g.r*wc3.w, 0.f);
            uint32_t h01,l01,h23,l23;
            split2(hc0,hc1,h01,l01); split2(hc2,hc3,h23,l23);
            uint32_t off = (uint32_t)(m*HSTR + j0)*2;
            *(uint2*)(Hhi + off) = make_uint2(h01,h23);
            *(uint2*)(Hlo + off) = make_uint2(l01,l23);

            float4 wp0 = *(const float4*)(sWpf + j0);
            float4 wp1 = *(const float4*)(sWpf + 64 + j0);
            float4 wp2 = *(const float4*)(sWpf + 128 + j0);
            float4 wp3 = *(const float4*)(sWpf + 192 + j0);
            float4 wp4 = *(const float4*)(sWpf + 256 + j0);
            float4 bp4 = *(const float4*)(sbpf + j0);
            float q0 = fmaxf(bp4.x + g.rn*wp0.x + g.sth*wp1.x + g.cth*wp2.x + g.sph*wp3.x + g.cph*wp4.x, 0.f);
            float q1 = fmaxf(bp4.y + g.rn*wp0.y + g.sth*wp1.y + g.cth*wp2.y + g.sph*wp3.y + g.cph*wp4.y, 0.f);
            float q2 = fmaxf(bp4.z + g.rn*wp0.z + g.sth*wp1.z + g.cth*wp2.z + g.sph*wp3.z + g.cph*wp4.z, 0.f);
            float q3 = fmaxf(bp4.w + g.rn*wp0.w + g.sth*wp1.w + g.cth*wp2.w + g.sph*wp3.w + g.cph*wp4.w, 0.f);
            sHPf[(j0  )*HPROW + gp] = q0;
            sHPf[(j0+1)*HPROW + gp] = q1;
            sHPf[(j0+2)*HPROW + gp] = q2;
            sHPf[(j0+3)*HPROW + gp] = q3;
        }
    }
    __syncthreads();

    // u-phase: u_t[j,grp] = sum_k coef_t[k]*hp[j,k]; pack to bf16-split U tile [grp*4+t][j]
    {
        int jp = tid >> 3, grp = tid & 7;
        int j0 = jp*2;
        const float2* hv0 = (const float2*)(sHPf + (j0  )*HPROW + grp*GSTR);
        const float2* hv1 = (const float2*)(sHPf + (j0+1)*HPROW + grp*GSTR);
        float2 h0[8], h1[8];
#pragma unroll
        for (int i=0;i<8;i++){ h0[i]=hv0[i]; h1[i]=hv1[i]; }
        float u0[4], u1[4];
#pragma unroll
        for (int t=0;t<4;t++){
            const float2* cv = (const float2*)(sCc + t*144 + grp*GSTR);
            float a0=0.f, a1=0.f;
#pragma unroll
            for (int i=0;i<8;i++){
                float2 c=cv[i];
                a0 = fmaf(c.x,h0[i].x,fmaf(c.y,h0[i].y,a0));
                a1 = fmaf(c.x,h1[i].x,fmaf(c.y,h1[i].y,a1));
            }
            u0[t]=a0; u1[t]=a1;
        }
        char* Uhi = smc + SH_UHI;
        char* Ulo = smc + SH_ULO;
#pragma unroll
        for (int t=0;t<4;t++){
            uint32_t hp, lp; split2(u0[t], u1[t], hp, lp);
            uint32_t off = (uint32_t)((grp*4+t)*USTR + j0)*2;
            *(uint32_t*)(Uhi + off) = hp;
            *(uint32_t*)(Ulo + off) = lp;
        }
    }
    __syncthreads();   // HP scratch dead -> W tiles overlay

    // copy W tiles (cart rows k=0..63, polar rows k=64..127) into overlay; zero stats
    {
        int c = tid >> 2, q = tid & 3;
        const uint4* gh = (const uint4*)(g_Whi + c*128 + q*16);       // cart: k 0..63
        const uint4* gl = (const uint4*)(g_Wlo + c*128 + q*16);
        uint4* shh = (uint4*)(smc + SH_WCHI + (c*WSTR + q*16)*2);
        uint4* shl = (uint4*)(smc + SH_WCLO + (c*WSTR + q*16)*2);
#pragma unroll
        for (int i=0;i<2;i++){ shh[i]=gh[i]; shl[i]=gl[i]; }
        const uint4* gph = (const uint4*)(g_Whi + c*128 + 64 + q*16); // polar: k 64..127
        const uint4* gpl = (const uint4*)(g_Wlo + c*128 + 64 + q*16);
        uint4* sph = (uint4*)(smc + SH_WPHI + (c*WSTR + q*16)*2);
        uint4* spl = (uint4*)(smc + SH_WPLO + (c*WSTR + q*16)*2);
#pragma unroll
        for (int i=0;i<2;i++){ sph[i]=gph[i]; spl[i]=gpl[i]; }
    }
    if (tid < CC){ sCc[tid]=0.f; sCc[72+tid]=0.f; }
    __syncthreads();

    // V GEMM: V[64c][32(grp*4+t)] = Wp * U  (bf16 3-pass, fp32 out to sV)
    {
        int gq2 = lane >> 2;
        int t2 = (lane & 3) * 2;
        int c0 = (wid & 3) * 16;
        int nh = (wid >> 2) * 16;
        int r0 = c0 + gq2, r1 = r0 + 8;
        int lrow = lane & 7, lgrp = lane >> 3;

        uint32_t Ah[4][4], Al[4][4];
        {
            uint32_t arow = (uint32_t)(c0 + (lgrp & 1)*8 + lrow);
            uint32_t acol = (uint32_t)((lgrp >> 1) * 8);
            uint32_t bh = smem_u32(smc + SH_WPHI) + (arow*WSTR + acol)*2;
            uint32_t bl = smem_u32(smc + SH_WPLO) + (arow*WSTR + acol)*2;
#pragma unroll
            for (int ks=0; ks<4; ks++){
                LDSM_X4(Ah[ks][0],Ah[ks][1],Ah[ks][2],Ah[ks][3], bh + ks*32);
                LDSM_X4(Al[ks][0],Al[ks][1],Al[ks][2],Al[ks][3], bl + ks*32);
            }
        }
        uint32_t uhb = smem_u32(smc + SH_UHI);
        uint32_t ulb = smem_u32(smc + SH_ULO);
#pragma unroll
        for (int nt=0; nt<2; nt++){
            int pn = nh + nt*8;
            uint32_t badh = uhb + (uint32_t)((pn + lrow)*USTR + lgrp*8)*2;
            uint32_t badl = ulb + (uint32_t)((pn + lrow)*USTR + lgrp*8)*2;
            uint32_t Bh[8], Bl[8];
#pragma unroll
            for (int kq=0; kq<2; kq++){
                LDSM_X4(Bh[kq*4+0],Bh[kq*4+1],Bh[kq*4+2],Bh[kq*4+3], badh + kq*64);
                LDSM_X4(Bl[kq*4+0],Bl[kq*4+1],Bl[kq*4+2],Bl[kq*4+3], badl + kq*64);
            }
            float a0=0.f, a1=0.f, a2=0.f, a3=0.f;
#pragma unroll
            for (int ks=0; ks<4; ks++){
                uint32_t bh0 = Bh[2*ks], bh1 = Bh[2*ks+1];
                uint32_t bl0 = Bl[2*ks], bl1 = Bl[2*ks+1];
                MMA_BF16(a0,a1,a2,a3, Ah[ks][0],Ah[ks][1],Ah[ks][2],Ah[ks][3], bh0,bh1);
                MMA_BF16(a0,a1,a2,a3, Ah[ks][0],Ah[ks][1],Ah[ks][2],Ah[ks][3], bl0,bl1);
                MMA_BF16(a0,a1,a2,a3, Al[ks][0],Al[ks][1],Al[ks][2],Al[ks][3], bh0,bh1);
            }
            int col = pn + t2;
            *(float2*)(sV + r0*36 + col) = make_float2(a0,a1);
            *(float2*)(sV + r1*36 + col) = make_float2(a2,a3);
        }
    }
    __syncthreads();

    // main GEMM: cart (K=64) + epilogue adds bz + bp*sk + sum_t m_t*V_t
    {
        int gq2 = lane >> 2;
        int t2 = (lane & 3) * 2;
        int c0 = (wid & 3) * 16;
        int ph = (wid >> 2) * 64;
        int r0 = c0 + gq2, r1 = r0 + 8;
        int lrow = lane & 7, lgrp = lane >> 3;

        uint32_t Ah[4][4], Al[4][4];
        {
            uint32_t arow = (uint32_t)(c0 + (lgrp & 1)*8 + lrow);
            uint32_t acol = (uint32_t)((lgrp >> 1) * 8);
            uint32_t bh = smem_u32(smc + SH_WCHI) + (arow*WSTR + acol)*2;
            uint32_t bl = smem_u32(smc + SH_WCLO) + (arow*WSTR + acol)*2;
#pragma unroll
            for (int ks=0; ks<4; ks++){
                LDSM_X4(Ah[ks][0],Ah[ks][1],Ah[ks][2],Ah[ks][3], bh + ks*32);
                LDSM_X4(Al[ks][0],Al[ks][1],Al[ks][2],Al[ks][3], bl + ks*32);
            }
        }
        uint32_t hbase = smem_u32(smc + SH_HHI);
        uint32_t lbase = smem_u32(smc + SH_HLO);
        float bz0 = sbz[r0], bz1 = sbz[r1], bp0 = sbp[r0], bp1 = sbp[r1];
        float s10=0.f, s20=0.f, s11=0.f, s21=0.f;
#pragma unroll 1
        for (int nt=0; nt<8; nt++){
            int pn = ph + nt*8;
            uint32_t badh = hbase + (uint32_t)((pn + lrow)*HSTR + lgrp*8)*2;
            uint32_t badl = lbase + (uint32_t)((pn + lrow)*HSTR + lgrp*8)*2;
            uint32_t Bh[8], Bl[8];
#pragma unroll
            for (int kq=0; kq<2; kq++){
                LDSM_X4(Bh[kq*4+0],Bh[kq*4+1],Bh[kq*4+2],Bh[kq*4+3], badh + kq*64);
                LDSM_X4(Bl[kq*4+0],Bl[kq*4+1],Bl[kq*4+2],Bl[kq*4+3], badl + kq*64);
            }
            float a0=0.f, a1=0.f, a2=0.f, a3=0.f;
#pragma unroll
            for (int ks=0; ks<4; ks++){
                uint32_t bh0 = Bh[2*ks], bh1 = Bh[2*ks+1];
                uint32_t bl0 = Bl[2*ks], bl1 = Bl[2*ks+1];
                MMA_BF16(a0,a1,a2,a3, Ah[ks][0],Ah[ks][1],Ah[ks][2],Ah[ks][3], bh0,bh1);
                MMA_BF16(a0,a1,a2,a3, Ah[ks][0],Ah[ks][1],Ah[ks][2],Ah[ks][3], bl0,bl1);
                MMA_BF16(a0,a1,a2,a3, Al[ks][0],Al[ks][1],Al[ks][2],Al[ks][3], bh0,bh1);
            }
            int col = pn + t2;
            int g4 = (col >> 4) * 4;
            float4 m4a = *(const float4*)(sMK + col*4);
            float4 m4b = *(const float4*)(sMK + (col+1)*4);
            float4 v0 = *(const float4*)(sV + r0*36 + g4);
            float4 v1 = *(const float4*)(sV + r1*36 + g4);
            float sk0 = sSK[col], sk1 = sSK[col+1];
            float e00 = m4a.x*v0.x + m4a.y*v0.y + m4a.z*v0.z + m4a.w*v0.w;
            float e01 = m4b.x*v0.x + m4b.y*v0.y + m4b.z*v0.z + m4b.w*v0.w;
            float e10 = m4a.x*v1.x + m4a.y*v1.y + m4a.z*v1.z + m4a.w*v1.w;
            float e11 = m4b.x*v1.x + m4b.y*v1.y + m4b.z*v1.z + m4b.w*v1.w;
            float z00 = a0 + fmaf(bp0, sk0, bz0) + e00;
            float z01 = a1 + fmaf(bp0, sk1, bz0) + e01;
            float z10 = a2 + fmaf(bp1, sk0, bz1) + e10;
            float z11 = a3 + fmaf(bp1, sk1, bz1) + e11;
            *(float2*)(g_z1 + (size_t)r0*NPTS + p0 + col) = make_float2(z00,z01);
            *(float2*)(g_z1 + (size_t)r1*NPTS + p0 + col) = make_float2(z10,z11);
            s10 += z00+z01; s20 += z00*z00+z01*z01;
            s11 += z10+z11; s21 += z10*z10+z11*z11;
        }
        s10 += __shfl_xor_sync(0xffffffffu, s10, 1); s10 += __shfl_xor_sync(0xffffffffu, s10, 2);
        s20 += __shfl_xor_sync(0xffffffffu, s20, 1); s20 += __shfl_xor_sync(0xffffffffu, s20, 2);
        s11 += __shfl_xor_sync(0xffffffffu, s11, 1); s11 += __shfl_xor_sync(0xffffffffu, s11, 2);
        s21 += __shfl_xor_sync(0xffffffffu, s21, 1); s21 += __shfl_xor_sync(0xffffffffu, s21, 2);
        if ((lane & 3) == 0){
            atomicAdd(&sCc[r0], s10);      atomicAdd(&sCc[72+r0], s20);
            atomicAdd(&sCc[r1], s11);      atomicAdd(&sCc[72+r1], s21);
        }
    }
    __syncthreads();
    if (tid < CC){
        atomicAdd(&g_zs1[tid], (double)sCc[tid]);
        atomicAdd(&g_zs2[tid], (double)sCc[72+tid]);
    }
}

__global__ void bnstats_kernel(const float* __restrict__ ge_g, const float* __restrict__ ge_be){
    int c = threadIdx.x;
    if (c < CC){
        double mean = g_zs1[c]/(double)NPTS;
        double var  = g_zs2[c]/(double)NPTS - mean*mean;
        double a = (double)ge_g[c]/sqrt(var + 1e-5);
        g_alpha[c] = (float)a;
        g_beta[c]  = (float)((double)ge_be[c] - mean*a);
    }
}

// ---------------- final kernel ----------------
#define FSTR 72
#define F2STR 72
#define FH_HHI 0
#define FH_HLO 18432
#define FH_WHI 36864
#define FH_WLO 46080
#define FH_A   55296
#define FH_BV  55552
#define FH_B2  55808
#define FINAL_SMEM 56064

__global__ __launch_bounds__(256,2) void final_kernel(const float* __restrict__ ge_b2,
                                                      float* __restrict__ out){
    extern __shared__ char smc[];
    float* sa  = (float*)(smc + FH_A);
    float* sbv = (float*)(smc + FH_BV);
    float* sb2 = (float*)(smc + FH_B2);
    int tid = threadIdx.x;
    int wid = tid >> 5;
    int lane = tid & 31;

    {
        int c = tid >> 2, q = tid & 3;
        const uint4* gh = (const uint4*)(g_W2hi + c*64 + q*16);
        const uint4* gl = (const uint4*)(g_W2lo + c*64 + q*16);
        uint4* shh = (uint4*)(smc + FH_WHI + (c*F2STR + q*16)*2);
        uint4* shl = (uint4*)(smc + FH_WLO + (c*F2STR + q*16)*2);
#pragma unroll
        for (int i=0;i<2;i++){ shh[i]=gh[i]; shl[i]=gl[i]; }
    }
    if (tid < CC){ sa[tid]=g_alpha[tid]; sbv[tid]=g_beta[tid]; sb2[tid]=ge_b2[tid]; }
    __syncthreads();

    int p0 = blockIdx.x*128;

    {
        int m = tid & 127;
        int ch = (tid >> 7) * 32;
        char* Hhi = smc + FH_HHI;
        char* Hlo = smc + FH_HLO;
#pragma unroll 2
        for (int c=ch; c<ch+32; c+=4){
            float z0 = g_z1[(size_t)c*NPTS + p0 + m];
            float z1v = g_z1[(size_t)(c+1)*NPTS + p0 + m];
            float z2 = g_z1[(size_t)(c+2)*NPTS + p0 + m];
            float z3 = g_z1[(size_t)(c+3)*NPTS + p0 + m];
            float h0 = fmaxf(fmaf(z0, sa[c], sbv[c]), 0.f);
            float h1 = fmaxf(fmaf(z1v, sa[c+1], sbv[c+1]), 0.f);
            float h2 = fmaxf(fmaf(z2, sa[c+2], sbv[c+2]), 0.f);
            float h3 = fmaxf(fmaf(z3, sa[c+3], sbv[c+3]), 0.f);
            uint32_t h01,l01,h23,l23;
            split2(h0,h1,h01,l01); split2(h2,h3,h23,l23);
            uint32_t off = (uint32_t)(m*FSTR + c)*2;
            *(uint2*)(Hhi + off) = make_uint2(h01,h23);
            *(uint2*)(Hlo + off) = make_uint2(l01,l23);
        }
    }
    __syncthreads();

    {
        int g = lane >> 2;
        int t2 = (lane & 3) * 2;
        int c0 = (wid & 3) * 16;
        int ph = (wid >> 2) * 64;
        int r0 = c0 + g, r1 = c0 + g + 8;
        int lrow = lane & 7, lgrp = lane >> 3;

        uint32_t Ah[4][4], Al[4][4];
        {
            uint32_t arow = (uint32_t)(c0 + (lgrp & 1)*8 + lrow);
            uint32_t acol = (uint32_t)((lgrp >> 1) * 8);
            uint32_t bh = smem_u32(smc + FH_WHI) + (arow*F2STR + acol)*2;
            uint32_t bl = smem_u32(smc + FH_WLO) + (arow*F2STR + acol)*2;
#pragma unroll
            for (int ks=0; ks<4; ks++){
                LDSM_X4(Ah[ks][0],Ah[ks][1],Ah[ks][2],Ah[ks][3], bh + ks*32);
                LDSM_X4(Al[ks][0],Al[ks][1],Al[ks][2],Al[ks][3], bl + ks*32);
            }
        }
        uint32_t hbase = smem_u32(smc + FH_HHI);
        uint32_t lbase = smem_u32(smc + FH_HLO);
        float b0v = sb2[r0], b1v = sb2[r1];
        int b = p0 >> 16;
        int nk0 = p0 & 65535;
        float* ob = out + (size_t)b*CC*65536;
#pragma unroll 1
        for (int nt=0; nt<8; nt++){
            int pn = ph + nt*8;
            uint32_t badh = hbase + (uint32_t)((pn + lrow)*FSTR + lgrp*8)*2;
            uint32_t badl = lbase + (uint32_t)((pn + lrow)*FSTR + lgrp*8)*2;
            uint32_t Bh[8], Bl[8];
#pragma unroll
            for (int kq=0; kq<2; kq++){
                LDSM_X4(Bh[kq*4+0],Bh[kq*4+1],Bh[kq*4+2],Bh[kq*4+3], badh + kq*64);
                LDSM_X4(Bl[kq*4+0],Bl[kq*4+1],Bl[kq*4+2],Bl[kq*4+3], badl + kq*64);
            }
            float a0=0.f, a1=0.f, a2=0.f, a3=0.f;
#pragma unroll
            for (int ks=0; ks<4; ks++){
                uint32_t bh0 = Bh[2*ks], bh1 = Bh[2*ks+1];
                uint32_t bl0 = Bl[2*ks], bl1 = Bl[2*ks+1];
                MMA_BF16(a0,a1,a2,a3, Ah[ks][0],Ah[ks][1],Ah[ks][2],Ah[ks][3], bh0,bh1);
                MMA_BF16(a0,a1,a2,a3, Ah[ks][0],Ah[ks][1],Ah[ks][2],Ah[ks][3], bl0,bl1);
                MMA_BF16(a0,a1,a2,a3, Al[ks][0],Al[ks][1],Al[ks][2],Al[ks][3], bh0,bh1);
            }
            int col = pn + t2;
            *(float2*)(ob + (size_t)r0*65536 + nk0 + col) = make_float2(a0+b0v, a1+b0v);
            *(float2*)(ob + (size_t)r1*65536 + nk0 + col) = make_float2(a2+b1v, a3+b1v);
        }
    }
}

extern "C" void kernel_launch(void* const* d_in, const int* in_sizes, int n_in,
                              void* d_out, int out_size){
    const float* nxyz  = (const float*)d_in[0];
    const float* cxyz  = (const float*)d_in[1];
    const float* cf_w1 = (const float*)d_in[2];
    const float* cf_b1 = (const float*)d_in[3];
    const float* cf_g  = (const float*)d_in[4];
    const float* cf_be = (const float*)d_in[5];
    const float* cf_w2 = (const float*)d_in[6];
    const float* cf_b2 = (const float*)d_in[7];
    const float* pf_w1 = (const float*)d_in[8];
    const float* pf_b1 = (const float*)d_in[9];
    const float* pf_g  = (const float*)d_in[10];
    const float* pf_be = (const float*)d_in[11];
    const float* pf_w2 = (const float*)d_in[12];
    const float* pf_b2 = (const float*)d_in[13];
    const float* ac_w  = (const float*)d_in[14];
    const float* ac_b  = (const float*)d_in[15];
    const float* ap_w  = (const float*)d_in[16];
    const float* ap_b  = (const float*)d_in[17];
    const float* gamma = (const float*)d_in[18];
    const float* ge_w1 = (const float*)d_in[19];
    const float* ge_b1 = (const float*)d_in[20];
    const float* ge_g  = (const float*)d_in[21];
    const float* ge_be = (const float*)d_in[22];
    const float* ge_w2 = (const float*)d_in[23];
    const float* ge_b2 = (const float*)d_in[24];
    float* out = (float*)d_out;

    cudaFuncSetAttribute(main_kernel, cudaFuncAttributeMaxDynamicSharedMemorySize, MAIN_SMEM);
    cudaFuncSetAttribute(final_kernel, cudaFuncAttributeMaxDynamicSharedMemorySize, FINAL_SMEM);

    zero_kernel<<<1, 64>>>();
    moments_kernel<<<NPTS/256, 256>>>(nxyz, cxyz);
    setup_kernel<<<1, 256>>>(cf_w1, cf_b1, cf_g, cf_be, cf_w2, cf_b2,
                             pf_w1, pf_b1, pf_g, pf_be, pf_w2, pf_b2,
                             ac_w, ac_b, ap_w, ap_b, gamma,
                             ge_w1, ge_b1, ge_w2);
    main_kernel<<<NPTS/128, 256, MAIN_SMEM>>>(nxyz, cxyz);
    bnstats_kernel<<<1, 64>>>(ge_g, ge_be);
    final_kernel<<<NPTS/128, 256, FINAL_SMEM>>>(ge_b2, out);
}

// round 14
// speedup vs baseline: 1.6200x; 1.0275x over previous
#include <cuda_runtime.h>
#include <cuda_bf16.h>
#include <math.h>
#include <stdint.h>

#define BB 8
#define NN 4096
#define KK 16
#define CC 64
#define NPTS (BB*NN*KK)
#define EPSF 1e-6f
#define PI_F 3.14159265358979323846f

// ---------------- device globals ----------------
__device__ double g_mom[34];
__device__ double g_zs1[CC];
__device__ double g_zs2[CC];
__device__ float  g_WcfT[4*CC];
__device__ float  g_bcf[CC];
__device__ float  g_WpfT[5*CC];
__device__ float  g_bpf[CC];
__device__ float  g_Wmain[128*CC];   // [k][c]
__device__ float  g_bz[CC];
__device__ float  g_bp[CC];
__device__ float  g_alpha[CC];
__device__ float  g_beta[CC];
__device__ float  g_z1[CC*NPTS];     // [c][p]
// bf16 split weights [c][k] row-major (k 0..63 cart, 64..127 polar)
__device__ __nv_bfloat16 g_Whi[CC*128];
__device__ __nv_bfloat16 g_Wlo[CC*128];
__device__ __nv_bfloat16 g_W2hi[CC*CC];
__device__ __nv_bfloat16 g_W2lo[CC*CC];

// ---------------- helpers ----------------
#define MMA_BF16(d0,d1,d2,d3,a0,a1,a2,a3,b0,b1) \
    asm volatile("mma.sync.aligned.m16n8k16.row.col.f32.bf16.bf16.f32 " \
        "{%0,%1,%2,%3}, {%4,%5,%6,%7}, {%8,%9}, {%0,%1,%2,%3};" \
        : "+f"(d0),"+f"(d1),"+f"(d2),"+f"(d3) \
        : "r"(a0),"r"(a1),"r"(a2),"r"(a3),"r"(b0),"r"(b1))

#define LDSM_X4(r0,r1,r2,r3, addr) \
    asm volatile("ldmatrix.sync.aligned.m8n8.x4.shared.b16 {%0,%1,%2,%3}, [%4];" \
        : "=r"(r0),"=r"(r1),"=r"(r2),"=r"(r3) : "r"(addr))

__device__ __forceinline__ uint32_t smem_u32(const void* p){
    uint32_t a;
    asm("{ .reg .u64 t; cvta.to.shared.u64 t, %1; cvt.u32.u64 %0, t; }" : "=r"(a) : "l"(p));
    return a;
}

__device__ __forceinline__ uint32_t pack_bf(float v0, float v1){
    __nv_bfloat16 h0 = __float2bfloat16_rn(v0);
    __nv_bfloat16 h1 = __float2bfloat16_rn(v1);
    return (uint32_t)(*(uint16_t*)&h0) | ((uint32_t)(*(uint16_t*)&h1) << 16);
}
__device__ __forceinline__ void split2(float v0, float v1, uint32_t& hp, uint32_t& lp){
    __nv_bfloat16 h0 = __float2bfloat16_rn(v0);
    __nv_bfloat16 h1 = __float2bfloat16_rn(v1);
    float r0 = v0 - __bfloat162float(h0);
    float r1 = v1 - __bfloat162float(h1);
    hp = (uint32_t)(*(uint16_t*)&h0) | ((uint32_t)(*(uint16_t*)&h1) << 16);
    lp = pack_bf(r0, r1);
}

__device__ __forceinline__ float wsum32(float v){
#pragma unroll
    for (int m=1; m<32; m<<=1) v += __shfl_xor_sync(0xffffffffu, v, m);
    return v;
}
__device__ __forceinline__ float gsum16(float v){
#pragma unroll
    for (int m=1; m<16; m<<=1) v += __shfl_xor_sync(0xffffffffu, v, m);
    return v;
}
__device__ __forceinline__ int clampi(int x,int lo,int hi){return x<lo?lo:(x>hi?hi:x);}

struct Geo { float dx,dy,dz,r,rn,sth,cth,sph,cph,theta; };
__device__ __forceinline__ Geo geom(const float* __restrict__ nxyz,
                                    const float* __restrict__ cxyz, int p){
    int b = p>>16, n = (p>>4)&(NN-1), k = p&(KK-1);
    int cb = (b*3)*NN + n;
    float cx=cxyz[cb], cy=cxyz[cb+NN], cz=cxyz[cb+2*NN];
    int nb = ((b*3)*NN + n)*KK + k;
    Geo g;
    g.dx = nxyz[nb]         - cx;
    g.dy = nxyz[nb+NN*KK]   - cy;
    g.dz = nxyz[nb+2*NN*KK] - cz;
    float r = sqrtf(g.dx*g.dx + g.dy*g.dy + g.dz*g.dz); r = fmaxf(r, EPSF);
    float rho = fmaxf(sqrtf(g.dx*g.dx + g.dy*g.dy), EPSF);
    g.r = r;
    g.theta = atan2f(g.dy, g.dx);
    float phi = atan2f(g.dz, rho);
    float rmean = gsum16(r) * (1.0f/16.0f);
    g.rn = fminf(r/(rmean+EPSF), 3.0f) * (1.0f/3.0f);
    sincosf(g.theta, &g.sth, &g.cth);
    sincosf(phi, &g.sph, &g.cph);
    return g;
}
struct Mix { float c0,c1,c2,c3, m0,m1,m2,m3, s_k; };
__device__ __forceinline__ Mix make_mix(const Geo& g){
    float ridx = g.rn*(2.0f - 1e-6f);
    float aidx = ((g.theta + PI_F)*(0.5f/PI_F))*(12.0f - 1e-6f);
    float ri0f = floorf(ridx); float rw1 = ridx-ri0f, rw0 = 1.0f-rw1;
    int ri0 = clampi((int)ri0f,0,1), ri1 = clampi((int)ri0f+1,0,1);
    float ai0f = floorf(aidx); float aw1 = aidx-ai0f, aw0 = 1.0f-aw1;
    int ai0 = clampi((int)ai0f,0,11), ai1 = clampi((int)ai0f+1,0,11);
    float w00=rw0*aw0, w01=rw0*aw1, w10=rw1*aw0, w11=rw1*aw1;
    int c00=ri0*12+ai0, c01=ri0*12+ai1, c10=ri1*12+ai0, c11=ri1*12+ai1;
    int t0 = __shfl_sync(0xffffffffu, c00, 0, 16);
    int t1 = __shfl_sync(0xffffffffu, c01, 0, 16);
    int t2 = __shfl_sync(0xffffffffu, c10, 0, 16);
    int t3 = __shfl_sync(0xffffffffu, c11, 0, 16);
    Mix mx;
    mx.c0 = (c00==t0?w00:0.f)+(c01==t0?w01:0.f)+(c10==t0?w10:0.f)+(c11==t0?w11:0.f);
    mx.c1 = (c00==t1?w00:0.f)+(c01==t1?w01:0.f)+(c10==t1?w10:0.f)+(c11==t1?w11:0.f);
    mx.c2 = (c00==t2?w00:0.f)+(c01==t2?w01:0.f)+(c10==t2?w10:0.f)+(c11==t2?w11:0.f);
    mx.c3 = (c00==t3?w00:0.f)+(c01==t3?w01:0.f)+(c10==t3?w10:0.f)+(c11==t3?w11:0.f);
    float den0 = gsum16(mx.c0), den1 = gsum16(mx.c1);
    float den2 = gsum16(mx.c2), den3 = gsum16(mx.c3);
    mx.m0 = w00/fmaxf(den0,EPSF); mx.m1 = w01/fmaxf(den1,EPSF);
    mx.m2 = w10/fmaxf(den2,EPSF); mx.m3 = w11/fmaxf(den3,EPSF);
    mx.s_k = mx.m0*den0 + mx.m1*den1 + mx.m2*den2 + mx.m3*den3;
    return mx;
}

// ---------------- small kernels ----------------
__global__ void zero_kernel(){
    int t = threadIdx.x;
    if (t < 34) g_mom[t] = 0.0;
    if (t < CC) { g_zs1[t]=0.0; g_zs2[t]=0.0; }
}

// 8 points per thread, register accumulation, one reduction
__global__ __launch_bounds__(256) void moments_kernel(const float* __restrict__ nxyz,
                                                      const float* __restrict__ cxyz){
    __shared__ double smom[34];
    int tid = threadIdx.x;
    if (tid < 34) smom[tid] = 0.0;
    __syncthreads();
    float va[34];
#pragma unroll
    for (int i=0;i<34;i++) va[i]=0.f;
    int base = blockIdx.x*2048 + tid;
#pragma unroll 1
    for (int it=0; it<8; it++){
        Geo g = geom(nxyz, cxyz, base + it*256);
        float fc[4] = {g.dx, g.dy, g.dz, g.r};
        float fp[5] = {g.rn, g.sth, g.cth, g.sph, g.cph};
#pragma unroll
        for (int i=0;i<4;i++){
            va[i] += fc[i];
#pragma unroll
            for (int j=i;j<4;j++) va[4 + i*4 - (i*(i-1))/2 + (j-i)] += fc[i]*fc[j];
        }
#pragma unroll
        for (int i=0;i<5;i++){
            va[14+i] += fp[i];
#pragma unroll
            for (int j=i;j<5;j++) va[19 + i*5 - (i*(i-1))/2 + (j-i)] += fp[i]*fp[j];
        }
    }
#pragma unroll
    for (int i=0;i<34;i++){
        float s = wsum32(va[i]);
        if ((tid&31)==0) atomicAdd(&smom[i], (double)s);
    }
    __syncthreads();
    if (tid < 34) atomicAdd(&g_mom[tid], smom[tid]);
}

__global__ void setup_kernel(
    const float* __restrict__ cf_w1, const float* __restrict__ cf_b1,
    const float* __restrict__ cf_g,  const float* __restrict__ cf_be,
    const float* __restrict__ cf_w2, const float* __restrict__ cf_b2,
    const float* __restrict__ pf_w1, const float* __restrict__ pf_b1,
    const float* __restrict__ pf_g,  const float* __restrict__ pf_be,
    const float* __restrict__ pf_w2, const float* __restrict__ pf_b2,
    const float* __restrict__ ac_w,  const float* __restrict__ ac_b,
    const float* __restrict__ ap_w,  const float* __restrict__ ap_b,
    const float* __restrict__ gamma_p,
    const float* __restrict__ ge_w1, const float* __restrict__ ge_b1,
    const float* __restrict__ ge_w2)
{
    __shared__ float sT[CC*CC];
    __shared__ float sv1[CC], sv2[CC];
    int tid = threadIdx.x;
    float gam = gamma_p[0];
    const double inv = 1.0/(double)NPTS;

    if (tid < CC){
        { // cart BN fold
            double mu[4], cov[4][4];
#pragma unroll
            for (int i=0;i<4;i++) mu[i] = g_mom[i]*inv;
#pragma unroll
            for (int i=0;i<4;i++)
#pragma unroll
                for (int j=i;j<4;j++){
                    double c2 = g_mom[4 + i*4 - (i*(i-1))/2 + (j-i)]*inv - mu[i]*mu[j];
                    cov[i][j]=c2; cov[j][i]=c2;
                }
            double w[4], m=(double)cf_b1[tid], vv=0.0;
#pragma unroll
            for (int i=0;i<4;i++){ w[i]=(double)cf_w1[tid*4+i]; m += w[i]*mu[i]; }
#pragma unroll
            for (int i=0;i<4;i++)
#pragma unroll
                for (int j=0;j<4;j++) vv += w[i]*w[j]*cov[i][j];
            double al = (double)cf_g[tid]/sqrt(vv+1e-5);
#pragma unroll
            for (int i=0;i<4;i++) g_WcfT[i*CC+tid] = (float)(w[i]*al);
            g_bcf[tid] = (float)(((double)cf_b1[tid]-m)*al + (double)cf_be[tid]);
        }
        { // polar BN fold
            double mu[5], cov[5][5];
#pragma unroll
            for (int i=0;i<5;i++) mu[i] = g_mom[14+i]*inv;
#pragma unroll
            for (int i=0;i<5;i++)
#pragma unroll
                for (int j=i;j<5;j++){
                    double c2 = g_mom[19 + i*5 - (i*(i-1))/2 + (j-i)]*inv - mu[i]*mu[j];
                    cov[i][j]=c2; cov[j][i]=c2;
                }
            double w[5], m=(double)pf_b1[tid], vv=0.0;
#pragma unroll
            for (int i=0;i<5;i++){ w[i]=(double)pf_w1[tid*5+i]; m += w[i]*mu[i]; }
#pragma unroll
            for (int i=0;i<5;i++)
#pragma unroll
                for (int j=0;j<5;j++) vv += w[i]*w[j]*cov[i][j];
            double al = (double)pf_g[tid]/sqrt(vv+1e-5);
#pragma unroll
            for (int i=0;i<5;i++) g_WpfT[i*CC+tid] = (float)(w[i]*al);
            g_bpf[tid] = (float)(((double)pf_b1[tid]-m)*al + (double)pf_be[tid]);
        }
    }
    for (int e=tid;e<CC*CC;e+=blockDim.x){
        int m=e>>6, j=e&63; float s=0.f;
        for (int l=0;l<CC;l++) s += ac_w[m*CC+l]*cf_w2[l*CC+j];
        sT[e]=s;
    }
    __syncthreads();
    for (int e=tid;e<CC*CC;e+=blockDim.x){
        int c=e>>6, j=e&63; float s=0.f;
        for (int m=0;m<CC;m++) s += ge_w1[c*CC+m]*sT[m*CC+j];
        g_Wmain[j*CC+c]=s;
    }
    __syncthreads();
    for (int e=tid;e<CC*CC;e+=blockDim.x){
        int m=e>>6, j=e&63; float s=0.f;
        for (int l=0;l<CC;l++) s += ap_w[m*CC+l]*pf_w2[l*CC+j];
        sT[e]=s;
    }
    __syncthreads();
    for (int e=tid;e<CC*CC;e+=blockDim.x){
        int c=e>>6, j=e&63; float s=0.f;
        for (int m=0;m<CC;m++) s += ge_w1[c*CC+m]*sT[m*CC+j];
        g_Wmain[(64+j)*CC+c]=gam*s;
    }
    if (tid < CC){
        float s1 = ac_b[tid] + gam*ap_b[tid];
        for (int j=0;j<CC;j++) s1 += ac_w[tid*CC+j]*cf_b2[j];
        sv1[tid]=s1;
        float s2 = 0.f;
        for (int j=0;j<CC;j++) s2 += ap_w[tid*CC+j]*pf_b2[j];
        sv2[tid]=s2;
    }
    __syncthreads();
    if (tid < CC){
        float bz = ge_b1[tid], bp = 0.f;
        for (int m=0;m<CC;m++){ bz += ge_w1[tid*CC+m]*sv1[m]; bp += ge_w1[tid*CC+m]*sv2[m]; }
        g_bz[tid]=bz; g_bp[tid]=gam*bp;
    }
    __syncthreads();
    for (int e=tid; e<CC*128; e+=blockDim.x){
        int k = e & 127, c = e >> 7;
        float v = g_Wmain[k*CC + c];
        __nv_bfloat16 h = __float2bfloat16_rn(v);
        float rem = v - __bfloat162float(h);
        g_Whi[c*128 + k] = h;
        g_Wlo[c*128 + k] = __float2bfloat16_rn(rem);
    }
    for (int e=tid; e<CC*CC; e+=blockDim.x){
        int j = e & 63, c = e >> 6;
        float v = ge_w2[c*CC + j];
        __nv_bfloat16 h = __float2bfloat16_rn(v);
        float rem = v - __bfloat162float(h);
        g_W2hi[c*64 + j] = h;
        g_W2lo[c*64 + j] = __float2bfloat16_rn(rem);
    }
}

// ---------------- main kernel smem layout (bytes) ----------------
#define HSTR 72
#define WSTR 72
#define USTR 72
#define GSTR 18
#define HPROW 144
#define SH_HHI   0          // 128*144 = 18432
#define SH_HLO   18432      // -> 36864
#define SH_HP    36864      // 36864 -> 73728 (overlaid by W tiles after u-phase)
#define SH_WCHI  36864
#define SH_WCLO  46080
#define SH_WPHI  55296
#define SH_WPLO  64512
#define SH_UHI   73728
#define SH_ULO   78336
#define SH_V     82944
#define SH_CC    92160
#define SH_MK    94464
#define SH_SK    96512
#define SH_WCF   97024
#define SH_WPF   98048
#define SH_BCF   99328
#define SH_BPF   99584
#define SH_BZ    99840
#define SH_BP    100096
#define MAIN_SMEM 100352

__global__ __launch_bounds__(256,2) void main_kernel(const float* __restrict__ nxyz,
                                                     const float* __restrict__ cxyz){
    extern __shared__ char smc[];
    float* sHPf = (float*)(smc + SH_HP);
    float* sV   = (float*)(smc + SH_V);
    float* sCc  = (float*)(smc + SH_CC);
    float* sMK  = (float*)(smc + SH_MK);
    float* sSK  = (float*)(smc + SH_SK);
    float* sWcf = (float*)(smc + SH_WCF);
    float* sWpf = (float*)(smc + SH_WPF);
    float* sbcf = (float*)(smc + SH_BCF);
    float* sbpf = (float*)(smc + SH_BPF);
    float* sbz  = (float*)(smc + SH_BZ);
    float* sbp  = (float*)(smc + SH_BP);
    int tid = threadIdx.x;
    int wid = tid >> 5;
    int lane = tid & 31;

    for (int i=tid;i<4*CC;i+=256) sWcf[i]=g_WcfT[i];
    for (int i=tid;i<5*CC;i+=256) sWpf[i]=g_WpfT[i];
    if (tid < CC){
        sbcf[tid]=g_bcf[tid]; sbpf[tid]=g_bpf[tid];
        sbz[tid]=g_bz[tid];   sbp[tid]=g_bp[tid];
    }
    __syncthreads();

    int p0 = blockIdx.x*128;
    int m  = tid & 127;
    int gp = (m>>4)*GSTR + (m&15);
    int msw = m & 8;   // store swizzle bit

    // phase A: geometry + mix coefs
    Geo g = geom(nxyz, cxyz, p0 + m);
    Mix mx = make_mix(g);
    if (tid < 128){
        sCc[0*144 + gp] = mx.c0;  sCc[1*144 + gp] = mx.c1;
        sCc[2*144 + gp] = mx.c2;  sCc[3*144 + gp] = mx.c3;
        *(float4*)(sMK + m*4) = make_float4(mx.m0, mx.m1, mx.m2, mx.m3);
        sSK[m] = mx.s_k;
    }

    // phase B: first layers (cart -> H split tile (swizzled); polar -> fp32 padded staging)
    {
        int jh = (tid >> 7) * 32;
        char* Hhi = smc + SH_HHI;
        char* Hlo = smc + SH_HLO;
#pragma unroll 2
        for (int j0=jh; j0<jh+32; j0+=4){
            float4 wc0 = *(const float4*)(sWcf + j0);
            float4 wc1 = *(const float4*)(sWcf + 64 + j0);
            float4 wc2 = *(const float4*)(sWcf + 128 + j0);
            float4 wc3 = *(const float4*)(sWcf + 192 + j0);
            float4 bc  = *(const float4*)(sbcf + j0);
            float hc0 = fmaxf(bc.x + g.dx*wc0.x + g.dy*wc1.x + g.dz*wc2.x + g.r*wc3.x, 0.f);
            float hc1 = fmaxf(bc.y + g.dx*wc0.y + g.dy*wc1.y + g.dz*wc2.y + g.r*wc3.y, 0.f);
            float hc2 = fmaxf(bc.z + g.dx*wc0.z + g.dy*wc1.z + g.dz*wc2.z + g.r*wc3.z, 0.f);
            float hc3 = fmaxf(bc.w + g.dx*wc0.w + g.dy*wc1.w + g.dz*wc2.w + g.r*wc3.w, 0.f);
            uint32_t h01,l01,h23,l23;
            split2(hc0,hc1,h01,l01); split2(hc2,hc3,h23,l23);
            uint32_t off = (uint32_t)(m*HSTR + (j0 ^ msw))*2;
            *(uint2*)(Hhi + off) = make_uint2(h01,h23);
            *(uint2*)(Hlo + off) = make_uint2(l01,l23);

            float4 wp0 = *(const float4*)(sWpf + j0);
            float4 wp1 = *(const float4*)(sWpf + 64 + j0);
            float4 wp2 = *(const float4*)(sWpf + 128 + j0);
            float4 wp3 = *(const float4*)(sWpf + 192 + j0);
            float4 wp4 = *(const float4*)(sWpf + 256 + j0);
            float4 bp4 = *(const float4*)(sbpf + j0);
            float q0 = fmaxf(bp4.x + g.rn*wp0.x + g.sth*wp1.x + g.cth*wp2.x + g.sph*wp3.x + g.cph*wp4.x, 0.f);
            float q1 = fmaxf(bp4.y + g.rn*wp0.y + g.sth*wp1.y + g.cth*wp2.y + g.sph*wp3.y + g.cph*wp4.y, 0.f);
            float q2 = fmaxf(bp4.z + g.rn*wp0.z + g.sth*wp1.z + g.cth*wp2.z + g.sph*wp3.z + g.cph*wp4.z, 0.f);
            float q3 = fmaxf(bp4.w + g.rn*wp0.w + g.sth*wp1.w + g.cth*wp2.w + g.sph*wp3.w + g.cph*wp4.w, 0.f);
            sHPf[(j0  )*HPROW + gp] = q0;
            sHPf[(j0+1)*HPROW + gp] = q1;
            sHPf[(j0+2)*HPROW + gp] = q2;
            sHPf[(j0+3)*HPROW + gp] = q3;
        }
    }
    __syncthreads();

    // u-phase: u_t[j,grp] = sum_k coef_t[k]*hp[j,k]; pack to bf16-split U tile [grp*4+t][j]
    {
        int jp = tid >> 3, grp = tid & 7;
        int j0 = jp*2;
        const float2* hv0 = (const float2*)(sHPf + (j0  )*HPROW + grp*GSTR);
        const float2* hv1 = (const float2*)(sHPf + (j0+1)*HPROW + grp*GSTR);
        float2 h0[8], h1[8];
#pragma unroll
        for (int i=0;i<8;i++){ h0[i]=hv0[i]; h1[i]=hv1[i]; }
        float u0[4], u1[4];
#pragma unroll
        for (int t=0;t<4;t++){
            const float2* cv = (const float2*)(sCc + t*144 + grp*GSTR);
            float a0=0.f, a1=0.f;
#pragma unroll
            for (int i=0;i<8;i++){
                float2 c=cv[i];
                a0 = fmaf(c.x,h0[i].x,fmaf(c.y,h0[i].y,a0));
                a1 = fmaf(c.x,h1[i].x,fmaf(c.y,h1[i].y,a1));
            }
            u0[t]=a0; u1[t]=a1;
        }
        char* Uhi = smc + SH_UHI;
        char* Ulo = smc + SH_ULO;
#pragma unroll
        for (int t=0;t<4;t++){
            uint32_t hp, lp; split2(u0[t], u1[t], hp, lp);
            uint32_t off = (uint32_t)((grp*4+t)*USTR + j0)*2;
            *(uint32_t*)(Uhi + off) = hp;
            *(uint32_t*)(Ulo + off) = lp;
        }
    }
    __syncthreads();   // HP scratch dead -> W tiles overlay

    // copy W tiles into overlay; zero stats
    {
        int c = tid >> 2, q = tid & 3;
        const uint4* gh = (const uint4*)(g_Whi + c*128 + q*16);
        const uint4* gl = (const uint4*)(g_Wlo + c*128 + q*16);
        uint4* shh = (uint4*)(smc + SH_WCHI + (c*WSTR + q*16)*2);
        uint4* shl = (uint4*)(smc + SH_WCLO + (c*WSTR + q*16)*2);
#pragma unroll
        for (int i=0;i<2;i++){ shh[i]=gh[i]; shl[i]=gl[i]; }
        const uint4* gph = (const uint4*)(g_Whi + c*128 + 64 + q*16);
        const uint4* gpl = (const uint4*)(g_Wlo + c*128 + 64 + q*16);
        uint4* sph = (uint4*)(smc + SH_WPHI + (c*WSTR + q*16)*2);
        uint4* spl = (uint4*)(smc + SH_WPLO + (c*WSTR + q*16)*2);
#pragma unroll
        for (int i=0;i<2;i++){ sph[i]=gph[i]; spl[i]=gpl[i]; }
    }
    if (tid < CC){ sCc[tid]=0.f; sCc[72+tid]=0.f; }
    __syncthreads();

    // V GEMM: V[64c][32(grp*4+t)] = Wp * U
    {
        int gq2 = lane >> 2;
        int t2 = (lane & 3) * 2;
        int c0 = (wid & 3) * 16;
        int nh = (wid >> 2) * 16;
        int r0 = c0 + gq2, r1 = r0 + 8;
        int lrow = lane & 7, lgrp = lane >> 3;

        uint32_t Ah[4][4], Al[4][4];
        {
            uint32_t arow = (uint32_t)(c0 + (lgrp & 1)*8 + lrow);
            uint32_t acol = (uint32_t)((lgrp >> 1) * 8);
            uint32_t bh = smem_u32(smc + SH_WPHI) + (arow*WSTR + acol)*2;
            uint32_t bl = smem_u32(smc + SH_WPLO) + (arow*WSTR + acol)*2;
#pragma unroll
            for (int ks=0; ks<4; ks++){
                LDSM_X4(Ah[ks][0],Ah[ks][1],Ah[ks][2],Ah[ks][3], bh + ks*32);
                LDSM_X4(Al[ks][0],Al[ks][1],Al[ks][2],Al[ks][3], bl + ks*32);
            }
        }
        uint32_t uhb = smem_u32(smc + SH_UHI);
        uint32_t ulb = smem_u32(smc + SH_ULO);
#pragma unroll
        for (int nt=0; nt<2; nt++){
            int pn = nh + nt*8;
            uint32_t badh = uhb + (uint32_t)((pn + lrow)*USTR + lgrp*8)*2;
            uint32_t badl = ulb + (uint32_t)((pn + lrow)*USTR + lgrp*8)*2;
            uint32_t Bh[8], Bl[8];
#pragma unroll
            for (int kq=0; kq<2; kq++){
                LDSM_X4(Bh[kq*4+0],Bh[kq*4+1],Bh[kq*4+2],Bh[kq*4+3], badh + kq*64);
                LDSM_X4(Bl[kq*4+0],Bl[kq*4+1],Bl[kq*4+2],Bl[kq*4+3], badl + kq*64);
            }
            float a0=0.f, a1=0.f, a2=0.f, a3=0.f;
#pragma unroll
            for (int ks=0; ks<4; ks++){
                uint32_t bh0 = Bh[2*ks], bh1 = Bh[2*ks+1];
                uint32_t bl0 = Bl[2*ks], bl1 = Bl[2*ks+1];
                MMA_BF16(a0,a1,a2,a3, Ah[ks][0],Ah[ks][1],Ah[ks][2],Ah[ks][3], bh0,bh1);
                MMA_BF16(a0,a1,a2,a3, Ah[ks][0],Ah[ks][1],Ah[ks][2],Ah[ks][3], bl0,bl1);
                MMA_BF16(a0,a1,a2,a3, Al[ks][0],Al[ks][1],Al[ks][2],Al[ks][3], bh0,bh1);
            }
            int col = pn + t2;
            *(float2*)(sV + r0*36 + col) = make_float2(a0,a1);
            *(float2*)(sV + r1*36 + col) = make_float2(a2,a3);
        }
    }
    __syncthreads();

    // main GEMM: cart (K=64, swizzled H reads) + epilogue
    {
        int gq2 = lane >> 2;
        int t2 = (lane & 3) * 2;
        int c0 = (wid & 3) * 16;
        int ph = (wid >> 2) * 64;
        int r0 = c0 + gq2, r1 = r0 + 8;
        int lrow = lane & 7, lgrp = lane >> 3;

        uint32_t Ah[4][4], Al[4][4];
        {
            uint32_t arow = (uint32_t)(c0 + (lgrp & 1)*8 + lrow);
            uint32_t acol = (uint32_t)((lgrp >> 1) * 8);
            uint32_t bh = smem_u32(smc + SH_WCHI) + (arow*WSTR + acol)*2;
            uint32_t bl = smem_u32(smc + SH_WCLO) + (arow*WSTR + acol)*2;
#pragma unroll
            for (int ks=0; ks<4; ks++){
                LDSM_X4(Ah[ks][0],Ah[ks][1],Ah[ks][2],Ah[ks][3], bh + ks*32);
                LDSM_X4(Al[ks][0],Al[ks][1],Al[ks][2],Al[ks][3], bl + ks*32);
            }
        }
        uint32_t hbase = smem_u32(smc + SH_HHI);
        uint32_t lbase = smem_u32(smc + SH_HLO);
        float bz0 = sbz[r0], bz1 = sbz[r1], bp0 = sbp[r0], bp1 = sbp[r1];
        float s10=0.f, s20=0.f, s11=0.f, s21=0.f;
#pragma unroll 1
        for (int nt=0; nt<8; nt++){
            int pn = ph + nt*8;
            int csw = (lgrp*8) ^ (pn & 8);
            uint32_t badh = hbase + (uint32_t)((pn + lrow)*HSTR + csw)*2;
            uint32_t badl = lbase + (uint32_t)((pn + lrow)*HSTR + csw)*2;
            uint32_t Bh[8], Bl[8];
#pragma unroll
            for (int kq=0; kq<2; kq++){
                LDSM_X4(Bh[kq*4+0],Bh[kq*4+1],Bh[kq*4+2],Bh[kq*4+3], badh + kq*64);
                LDSM_X4(Bl[kq*4+0],Bl[kq*4+1],Bl[kq*4+2],Bl[kq*4+3], badl + kq*64);
            }
            float a0=0.f, a1=0.f, a2=0.f, a3=0.f;
#pragma unroll
            for (int ks=0; ks<4; ks++){
                uint32_t bh0 = Bh[2*ks], bh1 = Bh[2*ks+1];
                uint32_t bl0 = Bl[2*ks], bl1 = Bl[2*ks+1];
                MMA_BF16(a0,a1,a2,a3, Ah[ks][0],Ah[ks][1],Ah[ks][2],Ah[ks][3], bh0,bh1);
                MMA_BF16(a0,a1,a2,a3, Ah[ks][0],Ah[ks][1],Ah[ks][2],Ah[ks][3], bl0,bl1);
                MMA_BF16(a0,a1,a2,a3, Al[ks][0],Al[ks][1],Al[ks][2],Al[ks][3], bh0,bh1);
            }
            int col = pn + t2;
            int g4 = (col >> 4) * 4;
            float4 m4a = *(const float4*)(sMK + col*4);
            float4 m4b = *(const float4*)(sMK + (col+1)*4);
            float4 v0 = *(const float4*)(sV + r0*36 + g4);
            float4 v1 = *(const float4*)(sV + r1*36 + g4);
            float sk0 = sSK[col], sk1 = sSK[col+1];
            float e00 = m4a.x*v0.x + m4a.y*v0.y + m4a.z*v0.z + m4a.w*v0.w;
            float e01 = m4b.x*v0.x + m4b.y*v0.y + m4b.z*v0.z + m4b.w*v0.w;
            float e10 = m4a.x*v1.x + m4a.y*v1.y + m4a.z*v1.z + m4a.w*v1.w;
            float e11 = m4b.x*v1.x + m4b.y*v1.y + m4b.z*v1.z + m4b.w*v1.w;
            float z00 = a0 + fmaf(bp0, sk0, bz0) + e00;
            float z01 = a1 + fmaf(bp0, sk1, bz0) + e01;
            float z10 = a2 + fmaf(bp1, sk0, bz1) + e10;
            float z11 = a3 + fmaf(bp1, sk1, bz1) + e11;
            *(float2*)(g_z1 + (size_t)r0*NPTS + p0 + col) = make_float2(z00,z01);
            *(float2*)(g_z1 + (size_t)r1*NPTS + p0 + col) = make_float2(z10,z11);
            s10 += z00+z01; s20 += z00*z00+z01*z01;
            s11 += z10+z11; s21 += z10*z10+z11*z11;
        }
        s10 += __shfl_xor_sync(0xffffffffu, s10, 1); s10 += __shfl_xor_sync(0xffffffffu, s10, 2);
        s20 += __shfl_xor_sync(0xffffffffu, s20, 1); s20 += __shfl_xor_sync(0xffffffffu, s20, 2);
        s11 += __shfl_xor_sync(0xffffffffu, s11, 1); s11 += __shfl_xor_sync(0xffffffffu, s11, 2);
        s21 += __shfl_xor_sync(0xffffffffu, s21, 1); s21 += __shfl_xor_sync(0xffffffffu, s21, 2);
        if ((lane & 3) == 0){
            atomicAdd(&sCc[r0], s10);      atomicAdd(&sCc[72+r0], s20);
            atomicAdd(&sCc[r1], s11);      atomicAdd(&sCc[72+r1], s21);
        }
    }
    __syncthreads();
    if (tid < CC){
        atomicAdd(&g_zs1[tid], (double)sCc[tid]);
        atomicAdd(&g_zs2[tid], (double)sCc[72+tid]);
    }
}

__global__ void bnstats_kernel(const float* __restrict__ ge_g, const float* __restrict__ ge_be){
    int c = threadIdx.x;
    if (c < CC){
        double mean = g_zs1[c]/(double)NPTS;
        double var  = g_zs2[c]/(double)NPTS - mean*mean;
        double a = (double)ge_g[c]/sqrt(var + 1e-5);
        g_alpha[c] = (float)a;
        g_beta[c]  = (float)((double)ge_be[c] - mean*a);
    }
}

// ---------------- final kernel ----------------
#define FSTR 72
#define F2STR 72
#define FH_HHI 0
#define FH_HLO 18432
#define FH_WHI 36864
#define FH_WLO 46080
#define FH_A   55296
#define FH_BV  55552
#define FH_B2  55808
#define FINAL_SMEM 56064

__global__ __launch_bounds__(256,2) void final_kernel(const float* __restrict__ ge_b2,
                                                      float* __restrict__ out){
    extern __shared__ char smc[];
    float* sa  = (float*)(smc + FH_A);
    float* sbv = (float*)(smc + FH_BV);
    float* sb2 = (float*)(smc + FH_B2);
    int tid = threadIdx.x;
    int wid = tid >> 5;
    int lane = tid & 31;

    {
        int c = tid >> 2, q = tid & 3;
        const uint4* gh = (const uint4*)(g_W2hi + c*64 + q*16);
        const uint4* gl = (const uint4*)(g_W2lo + c*64 + q*16);
        uint4* shh = (uint4*)(smc + FH_WHI + (c*F2STR + q*16)*2);
        uint4* shl = (uint4*)(smc + FH_WLO + (c*F2STR + q*16)*2);
#pragma unroll
        for (int i=0;i<2;i++){ shh[i]=gh[i]; shl[i]=gl[i]; }
    }
    if (tid < CC){ sa[tid]=g_alpha[tid]; sbv[tid]=g_beta[tid]; sb2[tid]=ge_b2[tid]; }
    __syncthreads();

    int p0 = blockIdx.x*128;

    {
        int m = tid & 127;
        int msw = m & 8;
        int ch = (tid >> 7) * 32;
        char* Hhi = smc + FH_HHI;
        char* Hlo = smc + FH_HLO;
#pragma unroll 2
        for (int c=ch; c<ch+32; c+=4){
            float z0 = g_z1[(size_t)c*NPTS + p0 + m];
            float z1v = g_z1[(size_t)(c+1)*NPTS + p0 + m];
            float z2 = g_z1[(size_t)(c+2)*NPTS + p0 + m];
            float z3 = g_z1[(size_t)(c+3)*NPTS + p0 + m];
            float h0 = fmaxf(fmaf(z0, sa[c], sbv[c]), 0.f);
            float h1 = fmaxf(fmaf(z1v, sa[c+1], sbv[c+1]), 0.f);
            float h2 = fmaxf(fmaf(z2, sa[c+2], sbv[c+2]), 0.f);
            float h3 = fmaxf(fmaf(z3, sa[c+3], sbv[c+3]), 0.f);
            uint32_t h01,l01,h23,l23;
            split2(h0,h1,h01,l01); split2(h2,h3,h23,l23);
            uint32_t off = (uint32_t)(m*FSTR + (c ^ msw))*2;
            *(uint2*)(Hhi + off) = make_uint2(h01,h23);
            *(uint2*)(Hlo + off) = make_uint2(l01,l23);
        }
    }
    __syncthreads();

    {
        int g = lane >> 2;
        int t2 = (lane & 3) * 2;
        int c0 = (wid & 3) * 16;
        int ph = (wid >> 2) * 64;
        int r0 = c0 + g, r1 = c0 + g + 8;
        int lrow = lane & 7, lgrp = lane >> 3;

        uint32_t Ah[4][4], Al[4][4];
        {
            uint32_t arow = (uint32_t)(c0 + (lgrp & 1)*8 + lrow);
            uint32_t acol = (uint32_t)((lgrp >> 1) * 8);
            uint32_t bh = smem_u32(smc + FH_WHI) + (arow*F2STR + acol)*2;
            uint32_t bl = smem_u32(smc + FH_WLO) + (arow*F2STR + acol)*2;
#pragma unroll
            for (int ks=0; ks<4; ks++){
                LDSM_X4(Ah[ks][0],Ah[ks][1],Ah[ks][2],Ah[ks][3], bh + ks*32);
                LDSM_X4(Al[ks][0],Al[ks][1],Al[ks][2],Al[ks][3], bl + ks*32);
            }
        }
        uint32_t hbase = smem_u32(smc + FH_HHI);
        uint32_t lbase = smem_u32(smc + FH_HLO);
        float b0v = sb2[r0], b1v = sb2[r1];
        int b = p0 >> 16;
        int nk0 = p0 & 65535;
        float* ob = out + (size_t)b*CC*65536;
#pragma unroll 1
        for (int nt=0; nt<8; nt++){
            int pn = ph + nt*8;
            int csw = (lgrp*8) ^ (pn & 8);
            uint32_t badh = hbase + (uint32_t)((pn + lrow)*FSTR + csw)*2;
            uint32_t badl = lbase + (uint32_t)((pn + lrow)*FSTR + csw)*2;
            uint32_t Bh[8], Bl[8];
#pragma unroll
            for (int kq=0; kq<2; kq++){
                LDSM_X4(Bh[kq*4+0],Bh[kq*4+1],Bh[kq*4+2],Bh[kq*4+3], badh + kq*64);
                LDSM_X4(Bl[kq*4+0],Bl[kq*4+1],Bl[kq*4+2],Bl[kq*4+3], badl + kq*64);
            }
            float a0=0.f, a1=0.f, a2=0.f, a3=0.f;
#pragma unroll
            for (int ks=0; ks<4; ks++){
                uint32_t bh0 = Bh[2*ks], bh1 = Bh[2*ks+1];
                uint32_t bl0 = Bl[2*ks], bl1 = Bl[2*ks+1];
                MMA_BF16(a0,a1,a2,a3, Ah[ks][0],Ah[ks][1],Ah[ks][2],Ah[ks][3], bh0,bh1);
                MMA_BF16(a0,a1,a2,a3, Ah[ks][0],Ah[ks][1],Ah[ks][2],Ah[ks][3], bl0,bl1);
                MMA_BF16(a0,a1,a2,a3, Al[ks][0],Al[ks][1],Al[ks][2],Al[ks][3], bh0,bh1);
            }
            int col = pn + t2;
            *(float2*)(ob + (size_t)r0*65536 + nk0 + col) = make_float2(a0+b0v, a1+b0v);
            *(float2*)(ob + (size_t)r1*65536 + nk0 + col) = make_float2(a2+b1v, a3+b1v);
        }
    }
}

extern "C" void kernel_launch(void* const* d_in, const int* in_sizes, int n_in,
                              void* d_out, int out_size){
    const float* nxyz  = (const float*)d_in[0];
    const float* cxyz  = (const float*)d_in[1];
    const float* cf_w1 = (const float*)d_in[2];
    const float* cf_b1 = (const float*)d_in[3];
    const float* cf_g  = (const float*)d_in[4];
    const float* cf_be = (const float*)d_in[5];
    const float* cf_w2 = (const float*)d_in[6];
    const float* cf_b2 = (const float*)d_in[7];
    const float* pf_w1 = (const float*)d_in[8];
    const float* pf_b1 = (const float*)d_in[9];
    const float* pf_g  = (const float*)d_in[10];
    const float* pf_be = (const float*)d_in[11];
    const float* pf_w2 = (const float*)d_in[12];
    const float* pf_b2 = (const float*)d_in[13];
    const float* ac_w  = (const float*)d_in[14];
    const float* ac_b  = (const float*)d_in[15];
    const float* ap_w  = (const float*)d_in[16];
    const float* ap_b  = (const float*)d_in[17];
    const float* gamma = (const float*)d_in[18];
    const float* ge_w1 = (const float*)d_in[19];
    const float* ge_b1 = (const float*)d_in[20];
    const float* ge_g  = (const float*)d_in[21];
    const float* ge_be = (const float*)d_in[22];
    const float* ge_w2 = (const float*)d_in[23];
    const float* ge_b2 = (const float*)d_in[24];
    float* out = (float*)d_out;

    cudaFuncSetAttribute(main_kernel, cudaFuncAttributeMaxDynamicSharedMemorySize, MAIN_SMEM);
    cudaFuncSetAttribute(final_kernel, cudaFuncAttributeMaxDynamicSharedMemorySize, FINAL_SMEM);

    zero_kernel<<<1, 64>>>();
    moments_kernel<<<NPTS/2048, 256>>>(nxyz, cxyz);
    setup_kernel<<<1, 256>>>(cf_w1, cf_b1, cf_g, cf_be, cf_w2, cf_b2,
                             pf_w1, pf_b1, pf_g, pf_be, pf_w2, pf_b2,
                             ac_w, ac_b, ap_w, ap_b, gamma,
                             ge_w1, ge_b1, ge_w2);
    main_kernel<<<NPTS/128, 256, MAIN_SMEM>>>(nxyz, cxyz);
    bnstats_kernel<<<1, 64>>>(ge_g, ge_be);
    final_kernel<<<NPTS/128, 256, FINAL_SMEM>>>(ge_b2, out);
}